// round 1
// baseline (speedup 1.0000x reference)
#include <cuda_runtime.h>
#include <math.h>

#define SEQ 1024
#define HDIM 1024
#define NHEADS 16
#define KVHEADS 8
#define GRP 2
#define HSZ 64
#define NEXP 64
#define TOPK 8
#define CAP 512
#define IDIM 3072
#define EPSF 1e-6f

// ---------------- scratch (device globals; no allocations allowed) ----------------
__device__ float g_x[SEQ * HDIM];
__device__ float g_qkv[SEQ * 2048];
__device__ float g_q[NHEADS * SEQ * HSZ];
__device__ float g_kT[KVHEADS * HSZ * SEQ];   // [kv][d][s]
__device__ float g_v[KVHEADS * SEQ * HSZ];
__device__ float g_scores[(size_t)NHEADS * SEQ * SEQ];
__device__ float g_attn[SEQ * HDIM];
__device__ float g_h1[SEQ * HDIM];
__device__ float g_x2[SEQ * HDIM];
__device__ float g_gu[SEQ * 2 * IDIM];
__device__ float g_hs[SEQ * IDIM];
__device__ float g_sharedo[SEQ * HDIM];
__device__ float g_logits[SEQ * NEXP];
__device__ int   g_assign_e[SEQ * TOPK];
__device__ float g_assign_w[SEQ * TOPK];
__device__ int   g_assign_p[SEQ * TOPK];
__device__ int   g_slot_token[NEXP * CAP];
__device__ int   g_count[NEXP];
__device__ float g_gue[(size_t)NEXP * CAP * 2 * IDIM];   // 768 MB
__device__ float g_hexp[(size_t)NEXP * CAP * IDIM];      // 384 MB
__device__ float g_ye[(size_t)NEXP * CAP * HDIM];        // 128 MB

// ---------------- rmsnorm ----------------
__global__ void rmsnorm_kernel(const float* __restrict__ in, const float* __restrict__ w,
                               float* __restrict__ out) {
    int row = blockIdx.x;
    const float* x = in + (size_t)row * HDIM;
    float* o = out + (size_t)row * HDIM;
    __shared__ float red[256];
    float s = 0.f;
    for (int i = threadIdx.x; i < HDIM; i += 256) { float v = x[i]; s += v * v; }
    red[threadIdx.x] = s; __syncthreads();
    for (int st = 128; st > 0; st >>= 1) {
        if (threadIdx.x < st) red[threadIdx.x] += red[threadIdx.x + st];
        __syncthreads();
    }
    float inv = rsqrtf(red[0] / (float)HDIM + EPSF);
    for (int i = threadIdx.x; i < HDIM; i += 256) o[i] = w[i] * x[i] * inv;
}

// ---------------- generic tiled SGEMM (row-major A[M,K] @ B[K,N]) ----------------
// 128x128 tile, BK=8, 256 threads, 8x8 per thread. M must be multiple of 128, K of 8, N of 4.
template <bool RES>
__global__ void sgemm_kernel(const float* __restrict__ A, const float* __restrict__ B,
                             float* __restrict__ C, const float* __restrict__ res,
                             int M, int N, int K, int lda, int ldb, int ldc,
                             long sA, long sB, long sC, int bdiv) {
    int z = blockIdx.z;
    A += (size_t)z * sA;
    B += (size_t)(z / bdiv) * sB;
    C += (size_t)z * sC;
    if (RES) res += (size_t)z * sC;
    __shared__ float As[8][128];
    __shared__ float Bs[8][128];
    int tid = threadIdx.x;
    int tx = tid & 15, ty = tid >> 4;
    int row0 = blockIdx.y * 128, col0 = blockIdx.x * 128;
    int arow = tid >> 1;
    int acol = (tid & 1) * 4;
    int brow = tid >> 5;
    int bcol = (tid & 31) * 4;
    const float* Aptr = A + (size_t)(row0 + arow) * lda + acol;
    const float* Bptr = B + (size_t)brow * ldb + col0 + bcol;
    bool bok = (col0 + bcol) < N;
    float acc[8][8];
#pragma unroll
    for (int i = 0; i < 8; i++)
#pragma unroll
        for (int j = 0; j < 8; j++) acc[i][j] = 0.f;

    for (int k0 = 0; k0 < K; k0 += 8) {
        float4 av = *(const float4*)(Aptr + k0);
        As[acol + 0][arow] = av.x;
        As[acol + 1][arow] = av.y;
        As[acol + 2][arow] = av.z;
        As[acol + 3][arow] = av.w;
        float4 bv = make_float4(0.f, 0.f, 0.f, 0.f);
        if (bok) bv = *(const float4*)(Bptr + (size_t)k0 * ldb);
        *(float4*)&Bs[brow][bcol] = bv;
        __syncthreads();
#pragma unroll
        for (int kk = 0; kk < 8; kk++) {
            float am[8], bn[8];
#pragma unroll
            for (int i = 0; i < 8; i++) am[i] = As[kk][ty * 8 + i];
#pragma unroll
            for (int j = 0; j < 8; j++) bn[j] = Bs[kk][tx * 8 + j];
#pragma unroll
            for (int i = 0; i < 8; i++)
#pragma unroll
                for (int j = 0; j < 8; j++) acc[i][j] += am[i] * bn[j];
        }
        __syncthreads();
    }
#pragma unroll
    for (int i = 0; i < 8; i++) {
        int r = row0 + ty * 8 + i;
#pragma unroll
        for (int j = 0; j < 8; j++) {
            int c = col0 + tx * 8 + j;
            if (c < N) {
                float v = acc[i][j];
                if (RES) v += res[(size_t)r * ldc + c];
                C[(size_t)r * ldc + c] = v;
            }
        }
    }
}

// ---------------- expert SGEMM with per-expert row tiles + optional gather ----------------
// grid.y = 256 tiles: expert = t>>2, slot0 = (t&3)*128. Skips tiles past count[e].
template <bool GATHER>
__global__ void sgemm_expert_kernel(const float* __restrict__ A, const float* __restrict__ B,
                                    float* __restrict__ C, int N, int K) {
    int t = blockIdx.y;
    int e = t >> 2;
    int slot0 = (t & 3) * 128;
    int cnt = g_count[e];
    if (slot0 >= cnt) return;
    B += (size_t)e * K * N;
    __shared__ float As[8][128];
    __shared__ float Bs[8][128];
    int tid = threadIdx.x;
    int tx = tid & 15, ty = tid >> 4;
    int col0 = blockIdx.x * 128;
    int arow = tid >> 1;
    int acol = (tid & 1) * 4;
    int brow = tid >> 5;
    int bcol = (tid & 31) * 4;
    int slot = slot0 + arow;
    bool aok = slot < cnt;
    const float* Aptr;
    if (GATHER) {
        int tok = aok ? g_slot_token[e * CAP + slot] : 0;
        Aptr = A + (size_t)tok * K + acol;
    } else {
        Aptr = A + (size_t)(e * CAP + slot) * K + acol;
    }
    const float* Bptr = B + (size_t)brow * N + col0 + bcol;
    float acc[8][8];
#pragma unroll
    for (int i = 0; i < 8; i++)
#pragma unroll
        for (int j = 0; j < 8; j++) acc[i][j] = 0.f;

    for (int k0 = 0; k0 < K; k0 += 8) {
        float4 av = make_float4(0.f, 0.f, 0.f, 0.f);
        if (aok) av = *(const float4*)(Aptr + k0);
        As[acol + 0][arow] = av.x;
        As[acol + 1][arow] = av.y;
        As[acol + 2][arow] = av.z;
        As[acol + 3][arow] = av.w;
        float4 bv = *(const float4*)(Bptr + (size_t)k0 * N);
        *(float4*)&Bs[brow][bcol] = bv;
        __syncthreads();
#pragma unroll
        for (int kk = 0; kk < 8; kk++) {
            float am[8], bn[8];
#pragma unroll
            for (int i = 0; i < 8; i++) am[i] = As[kk][ty * 8 + i];
#pragma unroll
            for (int j = 0; j < 8; j++) bn[j] = Bs[kk][tx * 8 + j];
#pragma unroll
            for (int i = 0; i < 8; i++)
#pragma unroll
                for (int j = 0; j < 8; j++) acc[i][j] += am[i] * bn[j];
        }
        __syncthreads();
    }
#pragma unroll
    for (int i = 0; i < 8; i++) {
        int r = e * CAP + slot0 + ty * 8 + i;
#pragma unroll
        for (int j = 0; j < 8; j++) {
            int c = col0 + tx * 8 + j;
            C[(size_t)r * N + c] = acc[i][j];
        }
    }
}

// ---------------- RoPE + qk rmsnorm + layout split ----------------
__global__ void rope_qk_kernel(const float* __restrict__ cosb, const float* __restrict__ sinb,
                               const float* __restrict__ qw, const float* __restrict__ kw) {
    int s = blockIdx.x, kv = blockIdx.y;
    int w = threadIdx.x >> 5, lane = threadIdx.x & 31;
    const float* src = g_qkv + (size_t)s * 2048 + kv * 256 + w * 64;
    float x1 = src[lane], x2 = src[lane + 32];
    float o1, o2;
    if (w < 3) {
        float c1 = cosb[s * 64 + lane], s1 = sinb[s * 64 + lane];
        float c2 = cosb[s * 64 + lane + 32], s2 = sinb[s * 64 + lane + 32];
        o1 = x1 * c1 - x2 * s1;
        o2 = x2 * c2 + x1 * s2;
        float ss = o1 * o1 + o2 * o2;
#pragma unroll
        for (int off = 16; off; off >>= 1) ss += __shfl_xor_sync(0xffffffffu, ss, off);
        float inv = rsqrtf(ss / 64.f + EPSF);
        const float* wt = (w < 2) ? qw : kw;
        o1 *= inv * wt[lane];
        o2 *= inv * wt[lane + 32];
    } else {
        o1 = x1; o2 = x2;
    }
    if (w < 2) {
        int head = kv * 2 + w;
        g_q[(size_t)head * 65536 + s * 64 + lane] = o1;
        g_q[(size_t)head * 65536 + s * 64 + lane + 32] = o2;
    } else if (w == 2) {
        g_kT[(size_t)kv * 65536 + lane * 1024 + s] = o1;
        g_kT[(size_t)kv * 65536 + (lane + 32) * 1024 + s] = o2;
    } else {
        g_v[(size_t)kv * 65536 + s * 64 + lane] = o1;
        g_v[(size_t)kv * 65536 + s * 64 + lane + 32] = o2;
    }
}

// ---------------- causal scaled softmax over scores rows ----------------
__global__ void softmax_kernel() {
    int s = blockIdx.x, h = blockIdx.y;
    float* row = g_scores + ((size_t)h * SEQ + s) * SEQ;
    int n = s + 1;
    __shared__ float red[256];
    int tid = threadIdx.x;
    float m = -INFINITY;
    for (int i = tid; i < n; i += 256) m = fmaxf(m, row[i] * 0.125f);
    red[tid] = m; __syncthreads();
    for (int st = 128; st > 0; st >>= 1) {
        if (tid < st) red[tid] = fmaxf(red[tid], red[tid + st]);
        __syncthreads();
    }
    m = red[0]; __syncthreads();
    float sum = 0.f;
    for (int i = tid; i < n; i += 256) {
        float p = __expf(row[i] * 0.125f - m);
        row[i] = p;
        sum += p;
    }
    red[tid] = sum; __syncthreads();
    for (int st = 128; st > 0; st >>= 1) {
        if (tid < st) red[tid] += red[tid + st];
        __syncthreads();
    }
    float inv = 1.f / red[0];
    for (int i = tid; i < n; i += 256) row[i] *= inv;
    for (int i = n + tid; i < SEQ; i += 256) row[i] = 0.f;
}

// ---------------- shared swiglu ----------------
__global__ void swiglu_shared_kernel() {
    int t = blockIdx.x;
    for (int i = threadIdx.x; i < IDIM; i += 256) {
        float a = g_gu[(size_t)t * 6144 + i];
        float b = g_gu[(size_t)t * 6144 + 3072 + i];
        g_hs[(size_t)t * 3072 + i] = a * (b / (1.f + __expf(-b)));
    }
}

// ---------------- gate softmax + top-8 ----------------
__global__ void topk_kernel() {
    int t = blockIdx.x;
    int tid = threadIdx.x;  // 64 threads
    __shared__ float gate[NEXP];
    __shared__ float red[NEXP];
    float lg = g_logits[t * NEXP + tid];
    red[tid] = lg; __syncthreads();
    for (int st = 32; st > 0; st >>= 1) {
        if (tid < st) red[tid] = fmaxf(red[tid], red[tid + st]);
        __syncthreads();
    }
    float m = red[0]; __syncthreads();
    float e = __expf(lg - m);
    gate[tid] = e;
    red[tid] = e; __syncthreads();
    for (int st = 32; st > 0; st >>= 1) {
        if (tid < st) red[tid] += red[tid + st];
        __syncthreads();
    }
    float inv = 1.f / red[0];
    __syncthreads();
    gate[tid] = e * inv;
    __syncthreads();
    if (tid == 0) {
        float vals[TOPK];
        int idxs[TOPK];
        float den = 0.f;
        for (int k = 0; k < TOPK; k++) {
            float bv = -INFINITY; int bi = 0;
            for (int i = 0; i < NEXP; i++) {
                float v = gate[i];
                if (v > bv) { bv = v; bi = i; }
            }
            vals[k] = bv; idxs[k] = bi; den += bv;
            gate[bi] = -INFINITY;
        }
        den = fmaxf(den, 1.19209290e-07f);
        for (int k = 0; k < TOPK; k++) {
            g_assign_e[t * TOPK + k] = idxs[k];
            g_assign_w[t * TOPK + k] = vals[k] / den;
        }
    }
}

// ---------------- routing: exact cumsum-order positions ----------------
__global__ void route_kernel() {
    int e = threadIdx.x;  // 64 threads, 1 block
    int cnt = 0;
    for (int i = 0; i < SEQ * TOPK; i++) {
        if (g_assign_e[i] == e) {
            g_assign_p[i] = cnt;
            if (cnt < CAP) g_slot_token[e * CAP + cnt] = i >> 3;
            cnt++;
        }
    }
    g_count[e] = cnt < CAP ? cnt : CAP;
}

// ---------------- expert swiglu (active rows only) ----------------
__global__ void swiglu_expert_kernel() {
    int t = blockIdx.x;
    int e = t >> 2;
    int slot0 = (t & 3) * 128 + blockIdx.y * 16;
    int cnt = g_count[e];
    if (slot0 >= cnt) return;
    int send = slot0 + 16;
    if (send > cnt) send = cnt;
    for (int slot = slot0; slot < send; slot++) {
        size_t r = (size_t)e * CAP + slot;
        for (int i = threadIdx.x; i < IDIM; i += 256) {
            float a = g_gue[r * 6144 + i];
            float b = g_gue[r * 6144 + 3072 + i];
            g_hexp[r * 3072 + i] = a * (b / (1.f + __expf(-b)));
        }
    }
}

// ---------------- final combine: out = h1 + shared + sum_k w*ye ----------------
__global__ void combine_kernel(float* __restrict__ out) {
    int t = blockIdx.x;
    int tid = threadIdx.x;
    __shared__ float w[TOPK];
    __shared__ int rr[TOPK];
    if (tid < TOPK) {
        int i = t * TOPK + tid;
        int p = g_assign_p[i];
        int e = g_assign_e[i];
        bool valid = p < CAP;
        w[tid] = valid ? g_assign_w[i] : 0.f;
        rr[tid] = e * CAP + (valid ? p : 0);
    }
    __syncthreads();
    for (int h = tid; h < HDIM; h += 256) {
        float v = g_h1[(size_t)t * HDIM + h] + g_sharedo[(size_t)t * HDIM + h];
#pragma unroll
        for (int k = 0; k < TOPK; k++) v += w[k] * g_ye[(size_t)rr[k] * HDIM + h];
        out[(size_t)t * HDIM + h] = v;
    }
}

// ---------------- launch ----------------
extern "C" void kernel_launch(void* const* d_in, const int* in_sizes, int n_in,
                              void* d_out, int out_size) {
    const float* hidden = (const float*)d_in[0];
    const float* cosb = (const float*)d_in[1];
    const float* sinb = (const float*)d_in[2];
    const float* ln1_w = (const float*)d_in[3];
    const float* ln2_w = (const float*)d_in[4];
    const float* Wqkv = (const float*)d_in[5];
    const float* Wo = (const float*)d_in[6];
    const float* qnorm_w = (const float*)d_in[7];
    const float* knorm_w = (const float*)d_in[8];
    const float* Wgu_sh = (const float*)d_in[9];
    const float* Wd_sh = (const float*)d_in[10];
    const float* Wgate = (const float*)d_in[11];
    const float* Wgu_ex = (const float*)d_in[12];
    const float* Wd_ex = (const float*)d_in[13];
    float* out = (float*)d_out;

    float *px, *pqkv, *pq, *pkT, *pv, *pscores, *pattn, *ph1, *px2, *pgu, *phs, *psh, *plog;
    float *pgue, *phexp, *pye;
    cudaGetSymbolAddress((void**)&px, g_x);
    cudaGetSymbolAddress((void**)&pqkv, g_qkv);
    cudaGetSymbolAddress((void**)&pq, g_q);
    cudaGetSymbolAddress((void**)&pkT, g_kT);
    cudaGetSymbolAddress((void**)&pv, g_v);
    cudaGetSymbolAddress((void**)&pscores, g_scores);
    cudaGetSymbolAddress((void**)&pattn, g_attn);
    cudaGetSymbolAddress((void**)&ph1, g_h1);
    cudaGetSymbolAddress((void**)&px2, g_x2);
    cudaGetSymbolAddress((void**)&pgu, g_gu);
    cudaGetSymbolAddress((void**)&phs, g_hs);
    cudaGetSymbolAddress((void**)&psh, g_sharedo);
    cudaGetSymbolAddress((void**)&plog, g_logits);
    cudaGetSymbolAddress((void**)&pgue, g_gue);
    cudaGetSymbolAddress((void**)&phexp, g_hexp);
    cudaGetSymbolAddress((void**)&pye, g_ye);

    // 1. x = rmsnorm(hidden, ln1)
    rmsnorm_kernel<<<SEQ, 256>>>(hidden, ln1_w, px);
    // 2. qkv = x @ Wqkv
    sgemm_kernel<false><<<dim3(16, 8, 1), 256>>>(px, Wqkv, pqkv, nullptr,
        1024, 2048, 1024, 1024, 2048, 2048, 0, 0, 0, 1);
    // 3. rope + qknorm + split
    rope_qk_kernel<<<dim3(SEQ, KVHEADS), 128>>>(cosb, sinb, qnorm_w, knorm_w);
    // 4. scores = q @ k^T (batched over heads, kv shared per 2 heads)
    sgemm_kernel<false><<<dim3(8, 8, NHEADS), 256>>>(pq, pkT, pscores, nullptr,
        1024, 1024, 64, 64, 1024, 1024, 65536, 65536, 1048576, 2);
    // 5. causal softmax (with 1/8 scale)
    softmax_kernel<<<dim3(SEQ, NHEADS), 256>>>();
    // 6. attn = P @ V  -> g_attn [S, NH*HD] via strideC=64
    sgemm_kernel<false><<<dim3(1, 8, NHEADS), 256>>>(pscores, pv, pattn, nullptr,
        1024, 64, 1024, 1024, 64, 1024, 1048576, 65536, 64, 2);
    // 7. h1 = attn @ Wo + hidden
    sgemm_kernel<true><<<dim3(8, 8, 1), 256>>>(pattn, Wo, ph1, hidden,
        1024, 1024, 1024, 1024, 1024, 1024, 0, 0, 0, 1);
    // 8. x2 = rmsnorm(h1, ln2)
    rmsnorm_kernel<<<SEQ, 256>>>(ph1, ln2_w, px2);
    // 9. gu = x2 @ Wgu_shared
    sgemm_kernel<false><<<dim3(48, 8, 1), 256>>>(px2, Wgu_sh, pgu, nullptr,
        1024, 6144, 1024, 1024, 6144, 6144, 0, 0, 0, 1);
    // 10. swiglu
    swiglu_shared_kernel<<<SEQ, 256>>>();
    // 11. shared = hs @ Wd_shared
    sgemm_kernel<false><<<dim3(8, 8, 1), 256>>>(phs, Wd_sh, psh, nullptr,
        1024, 1024, 3072, 3072, 1024, 1024, 0, 0, 0, 1);
    // 12. logits = x2 @ Wgate
    sgemm_kernel<false><<<dim3(1, 8, 1), 256>>>(px2, Wgate, plog, nullptr,
        1024, 64, 1024, 1024, 64, 64, 0, 0, 0, 1);
    // 13. softmax + top8 + normalize
    topk_kernel<<<SEQ, 64>>>();
    // 14. exact cumsum-order routing
    route_kernel<<<1, 64>>>();
    // 15. expert GEMM1 (gathered rows) -> gu_e
    sgemm_expert_kernel<true><<<dim3(48, 256), 256>>>(px2, Wgu_ex, pgue, 6144, 1024);
    // 16. expert swiglu
    swiglu_expert_kernel<<<dim3(256, 8), 256>>>();
    // 17. expert GEMM2 -> ye
    sgemm_expert_kernel<false><<<dim3(8, 256), 256>>>(phexp, Wd_ex, pye, 1024, 3072);
    // 18. out = h1 + shared + moe
    combine_kernel<<<SEQ, 256>>>(out);
}

// round 3
// speedup vs baseline: 1.7285x; 1.7285x over previous
#include <cuda_runtime.h>
#include <cuda_bf16.h>
#include <math.h>
#include <stdint.h>

#define SEQ 1024
#define HDIM 1024
#define NHEADS 16
#define KVHEADS 8
#define HSZ 64
#define NEXP 64
#define TOPK 8
#define CAP 512
#define IDIM 3072
#define EPSF 1e-6f

// ---------------- scratch ----------------
__device__ float g_x[SEQ * HDIM];
__device__ float g_qkv[SEQ * 2048];
__device__ float g_q[NHEADS * SEQ * HSZ];
__device__ float g_kT[KVHEADS * HSZ * SEQ];
__device__ float g_v[KVHEADS * SEQ * HSZ];
__device__ float g_scores[(size_t)NHEADS * SEQ * SEQ];
__device__ float g_attn[SEQ * HDIM];
__device__ float g_h1[SEQ * HDIM];
__device__ float g_x2[SEQ * HDIM];
__device__ float g_gu[SEQ * 2 * IDIM];
__device__ float g_hs[SEQ * IDIM];
__device__ float g_sharedo[SEQ * HDIM];
__device__ float g_logits[SEQ * NEXP];
__device__ int   g_assign_e[SEQ * TOPK];
__device__ float g_assign_w[SEQ * TOPK];
__device__ int   g_assign_p[SEQ * TOPK];
__device__ int   g_slot_token[NEXP * CAP];
__device__ int   g_count[NEXP];
__device__ float g_gue[(size_t)NEXP * CAP * 2 * IDIM];
__device__ float g_hexp[(size_t)NEXP * CAP * IDIM];
__device__ float g_ye[(size_t)NEXP * CAP * HDIM];

// ---------------- helpers ----------------
__device__ __forceinline__ uint32_t smem_u32(const void* p) {
    uint32_t a;
    asm("{ .reg .u64 t; cvta.to.shared.u64 t, %1; cvt.u32.u64 %0, t; }" : "=r"(a) : "l"(p));
    return a;
}
__device__ __forceinline__ uint32_t packbf(float a, float b) {
    __nv_bfloat162 t = __floats2bfloat162_rn(a, b);
    return *reinterpret_cast<uint32_t*>(&t);
}
__device__ __forceinline__ void split4(float4 v, uint2& h, uint2& l) {
    float hx = __bfloat162float(__float2bfloat16(v.x));
    float hy = __bfloat162float(__float2bfloat16(v.y));
    float hz = __bfloat162float(__float2bfloat16(v.z));
    float hw = __bfloat162float(__float2bfloat16(v.w));
    h.x = packbf(hx, hy);
    h.y = packbf(hz, hw);
    l.x = packbf(v.x - hx, v.y - hy);
    l.y = packbf(v.z - hz, v.w - hw);
}
__device__ __forceinline__ void ldmx4(uint32_t* r, uint32_t addr) {
    asm volatile("ldmatrix.sync.aligned.m8n8.x4.shared.b16 {%0,%1,%2,%3}, [%4];"
                 : "=r"(r[0]), "=r"(r[1]), "=r"(r[2]), "=r"(r[3]) : "r"(addr));
}
__device__ __forceinline__ void ldmx2t(uint32_t* r, uint32_t addr) {
    asm volatile("ldmatrix.sync.aligned.m8n8.x2.trans.shared.b16 {%0,%1}, [%2];"
                 : "=r"(r[0]), "=r"(r[1]) : "r"(addr));
}
__device__ __forceinline__ void mma16816(float* d, const uint32_t* a, const uint32_t* b) {
    asm volatile("mma.sync.aligned.m16n8k16.row.col.f32.bf16.bf16.f32 "
                 "{%0,%1,%2,%3}, {%4,%5,%6,%7}, {%8,%9}, {%0,%1,%2,%3};"
                 : "+f"(d[0]), "+f"(d[1]), "+f"(d[2]), "+f"(d[3])
                 : "r"(a[0]), "r"(a[1]), "r"(a[2]), "r"(a[3]), "r"(b[0]), "r"(b[1]));
}

// ---------------- bf16 split-precision HMMA GEMM ----------------
// C[M,N] = A[M,K] @ B[K,N] in fp32-equivalent accuracy (hi/lo bf16 split, 3 MMA passes).
// 128x128 tile, BK=32, 256 threads. MODE 0: dense; 1: expert+gather; 2: expert direct.
#define APAD 40
#define BPAD 136
template <int MODE, bool RES>
__global__ void __launch_bounds__(256) bf_gemm(const float* __restrict__ A,
                                               const float* __restrict__ B,
                                               float* __restrict__ C,
                                               const float* __restrict__ res,
                                               int N, int K) {
    __shared__ __align__(16) __nv_bfloat16 As_h[128][APAD];
    __shared__ __align__(16) __nv_bfloat16 As_l[128][APAD];
    __shared__ __align__(16) __nv_bfloat16 Bs_h[32][BPAD];
    __shared__ __align__(16) __nv_bfloat16 Bs_l[32][BPAD];

    int tid = threadIdx.x, lane = tid & 31, wid = tid >> 5;
    int wm = wid & 1, wn = wid >> 1;   // warp tile: rows wm*64, cols wn*32

    int e = 0, slot0 = 0, cnt = 128;
    size_t crow0;
    if (MODE == 0) {
        crow0 = (size_t)blockIdx.y * 128;
    } else {
        int t = blockIdx.y;
        e = t >> 2;
        slot0 = (t & 3) * 128;
        int c = g_count[e] - slot0;
        if (c <= 0) return;
        cnt = c < 128 ? c : 128;
        B += (size_t)e * K * N;
        crow0 = (size_t)e * CAP + slot0;
    }
    int n0 = blockIdx.x * 128;

    float acc[4][4][4];
#pragma unroll
    for (int i = 0; i < 4; i++)
#pragma unroll
        for (int j = 0; j < 4; j++)
#pragma unroll
            for (int v = 0; v < 4; v++) acc[i][j][v] = 0.f;

    uint32_t sAh = smem_u32(As_h), sAl = smem_u32(As_l);
    uint32_t sBh = smem_u32(Bs_h), sBl = smem_u32(Bs_l);

    for (int k0 = 0; k0 < K; k0 += 32) {
        // ---- stage A [128 x 32] fp32 -> bf16 hi/lo ----
#pragma unroll
        for (int j = 0; j < 4; j++) {
            int idx = tid + j * 256;
            int row = idx >> 3, q = (idx & 7) * 4;
            float4 v;
            if (MODE == 0) {
                v = *(const float4*)(A + (crow0 + row) * (size_t)K + k0 + q);
            } else if (MODE == 1) {
                if (row < cnt) {
                    int tok = g_slot_token[e * CAP + slot0 + row];
                    v = *(const float4*)(A + (size_t)tok * K + k0 + q);
                } else v = make_float4(0.f, 0.f, 0.f, 0.f);
            } else {
                v = (row < cnt) ? *(const float4*)(A + (crow0 + row) * (size_t)K + k0 + q)
                                : make_float4(0.f, 0.f, 0.f, 0.f);
            }
            uint2 h, l;
            split4(v, h, l);
            *(uint2*)&As_h[row][q] = h;
            *(uint2*)&As_l[row][q] = l;
        }
        // ---- stage B [32 x 128] fp32 -> bf16 hi/lo ----
#pragma unroll
        for (int j = 0; j < 4; j++) {
            int idx = tid + j * 256;
            int row = idx >> 5, q = (idx & 31) * 4;
            float4 v = *(const float4*)(B + (size_t)(k0 + row) * N + n0 + q);
            uint2 h, l;
            split4(v, h, l);
            *(uint2*)&Bs_h[row][q] = h;
            *(uint2*)&Bs_l[row][q] = l;
        }
        __syncthreads();

#pragma unroll
        for (int ks = 0; ks < 2; ks++) {
            uint32_t ah[4][4], al[4][4], bh[4][2], bl[4][2];
#pragma unroll
            for (int i = 0; i < 4; i++) {
                uint32_t off = ((wm * 64 + i * 16 + (lane & 15)) * APAD + ks * 16 + (lane >> 4) * 8) * 2;
                ldmx4(ah[i], sAh + off);
                ldmx4(al[i], sAl + off);
            }
#pragma unroll
            for (int j = 0; j < 4; j++) {
                uint32_t off = ((ks * 16 + (lane & 15)) * BPAD + wn * 32 + j * 8) * 2;
                ldmx2t(bh[j], sBh + off);
                ldmx2t(bl[j], sBl + off);
            }
#pragma unroll
            for (int i = 0; i < 4; i++)
#pragma unroll
                for (int j = 0; j < 4; j++) {
                    mma16816(acc[i][j], ah[i], bh[j]);
                    mma16816(acc[i][j], al[i], bh[j]);
                    mma16816(acc[i][j], ah[i], bl[j]);
                }
        }
        __syncthreads();
    }

    // ---- epilogue ----
#pragma unroll
    for (int i = 0; i < 4; i++) {
        int r0 = wm * 64 + i * 16 + (lane >> 2);
#pragma unroll
        for (int j = 0; j < 4; j++) {
            int c0 = n0 + wn * 32 + j * 8 + (lane & 3) * 2;
            float* cp = C + (crow0 + r0) * (size_t)N + c0;
            float* cp2 = C + (crow0 + r0 + 8) * (size_t)N + c0;
            if (RES) {
                const float* rp = res + (crow0 + r0) * (size_t)N + c0;
                const float* rp2 = res + (crow0 + r0 + 8) * (size_t)N + c0;
                cp[0] = acc[i][j][0] + rp[0];
                cp[1] = acc[i][j][1] + rp[1];
                cp2[0] = acc[i][j][2] + rp2[0];
                cp2[1] = acc[i][j][3] + rp2[1];
            } else {
                cp[0] = acc[i][j][0];
                cp[1] = acc[i][j][1];
                cp2[0] = acc[i][j][2];
                cp2[1] = acc[i][j][3];
            }
        }
    }
}

// ---------------- rmsnorm ----------------
__global__ void rmsnorm_kernel(const float* __restrict__ in, const float* __restrict__ w,
                               float* __restrict__ out) {
    int row = blockIdx.x;
    const float* x = in + (size_t)row * HDIM;
    float* o = out + (size_t)row * HDIM;
    __shared__ float red[256];
    float s = 0.f;
    for (int i = threadIdx.x; i < HDIM; i += 256) { float v = x[i]; s += v * v; }
    red[threadIdx.x] = s; __syncthreads();
    for (int st = 128; st > 0; st >>= 1) {
        if (threadIdx.x < st) red[threadIdx.x] += red[threadIdx.x + st];
        __syncthreads();
    }
    float inv = rsqrtf(red[0] / (float)HDIM + EPSF);
    for (int i = threadIdx.x; i < HDIM; i += 256) o[i] = w[i] * x[i] * inv;
}

// ---------------- fp32 SGEMM (attention + logits) ----------------
// KM 0: plain, 1: causal block-skip (scores), 2: K capped at row0+128 (P@V)
template <bool RES, int KM>
__global__ void sgemm_kernel(const float* __restrict__ A, const float* __restrict__ B,
                             float* __restrict__ C, const float* __restrict__ res,
                             int M, int N, int K, int lda, int ldb, int ldc,
                             long sA, long sB, long sC, int bdiv) {
    int z = blockIdx.z;
    int row0 = blockIdx.y * 128, col0 = blockIdx.x * 128;
    if (KM == 1 && col0 > row0) return;
    int Keff = K;
    if (KM == 2) Keff = (row0 + 128 < K) ? row0 + 128 : K;
    A += (size_t)z * sA;
    B += (size_t)(z / bdiv) * sB;
    C += (size_t)z * sC;
    if (RES) res += (size_t)z * sC;
    __shared__ float As[8][128];
    __shared__ float Bs[8][128];
    int tid = threadIdx.x;
    int tx = tid & 15, ty = tid >> 4;
    int arow = tid >> 1;
    int acol = (tid & 1) * 4;
    int brow = tid >> 5;
    int bcol = (tid & 31) * 4;
    const float* Aptr = A + (size_t)(row0 + arow) * lda + acol;
    const float* Bptr = B + (size_t)brow * ldb + col0 + bcol;
    bool bok = (col0 + bcol) < N;
    float acc[8][8];
#pragma unroll
    for (int i = 0; i < 8; i++)
#pragma unroll
        for (int j = 0; j < 8; j++) acc[i][j] = 0.f;

    for (int k0 = 0; k0 < Keff; k0 += 8) {
        float4 av = *(const float4*)(Aptr + k0);
        As[acol + 0][arow] = av.x;
        As[acol + 1][arow] = av.y;
        As[acol + 2][arow] = av.z;
        As[acol + 3][arow] = av.w;
        float4 bv = make_float4(0.f, 0.f, 0.f, 0.f);
        if (bok) bv = *(const float4*)(Bptr + (size_t)k0 * ldb);
        *(float4*)&Bs[brow][bcol] = bv;
        __syncthreads();
#pragma unroll
        for (int kk = 0; kk < 8; kk++) {
            float am[8], bn[8];
#pragma unroll
            for (int i = 0; i < 8; i++) am[i] = As[kk][ty * 8 + i];
#pragma unroll
            for (int j = 0; j < 8; j++) bn[j] = Bs[kk][tx * 8 + j];
#pragma unroll
            for (int i = 0; i < 8; i++)
#pragma unroll
                for (int j = 0; j < 8; j++) acc[i][j] += am[i] * bn[j];
        }
        __syncthreads();
    }
#pragma unroll
    for (int i = 0; i < 8; i++) {
        int r = row0 + ty * 8 + i;
#pragma unroll
        for (int j = 0; j < 8; j++) {
            int c = col0 + tx * 8 + j;
            if (c < N) {
                float v = acc[i][j];
                if (RES) v += res[(size_t)r * ldc + c];
                C[(size_t)r * ldc + c] = v;
            }
        }
    }
}

// ---------------- RoPE + qk rmsnorm + layout split ----------------
__global__ void rope_qk_kernel(const float* __restrict__ cosb, const float* __restrict__ sinb,
                               const float* __restrict__ qw, const float* __restrict__ kw) {
    int s = blockIdx.x, kv = blockIdx.y;
    int w = threadIdx.x >> 5, lane = threadIdx.x & 31;
    const float* src = g_qkv + (size_t)s * 2048 + kv * 256 + w * 64;
    float x1 = src[lane], x2 = src[lane + 32];
    float o1, o2;
    if (w < 3) {
        float c1 = cosb[s * 64 + lane], s1 = sinb[s * 64 + lane];
        float c2 = cosb[s * 64 + lane + 32], s2 = sinb[s * 64 + lane + 32];
        o1 = x1 * c1 - x2 * s1;
        o2 = x2 * c2 + x1 * s2;
        float ss = o1 * o1 + o2 * o2;
#pragma unroll
        for (int off = 16; off; off >>= 1) ss += __shfl_xor_sync(0xffffffffu, ss, off);
        float inv = rsqrtf(ss / 64.f + EPSF);
        const float* wt = (w < 2) ? qw : kw;
        o1 *= inv * wt[lane];
        o2 *= inv * wt[lane + 32];
    } else {
        o1 = x1; o2 = x2;
    }
    if (w < 2) {
        int head = kv * 2 + w;
        g_q[(size_t)head * 65536 + s * 64 + lane] = o1;
        g_q[(size_t)head * 65536 + s * 64 + lane + 32] = o2;
    } else if (w == 2) {
        g_kT[(size_t)kv * 65536 + lane * 1024 + s] = o1;
        g_kT[(size_t)kv * 65536 + (lane + 32) * 1024 + s] = o2;
    } else {
        g_v[(size_t)kv * 65536 + s * 64 + lane] = o1;
        g_v[(size_t)kv * 65536 + s * 64 + lane + 32] = o2;
    }
}

// ---------------- causal scaled softmax ----------------
__global__ void softmax_kernel() {
    int s = blockIdx.x, h = blockIdx.y;
    float* row = g_scores + ((size_t)h * SEQ + s) * SEQ;
    int n = s + 1;
    __shared__ float red[256];
    int tid = threadIdx.x;
    float m = -INFINITY;
    for (int i = tid; i < n; i += 256) m = fmaxf(m, row[i] * 0.125f);
    red[tid] = m; __syncthreads();
    for (int st = 128; st > 0; st >>= 1) {
        if (tid < st) red[tid] = fmaxf(red[tid], red[tid + st]);
        __syncthreads();
    }
    m = red[0]; __syncthreads();
    float sum = 0.f;
    for (int i = tid; i < n; i += 256) {
        float p = __expf(row[i] * 0.125f - m);
        row[i] = p;
        sum += p;
    }
    red[tid] = sum; __syncthreads();
    for (int st = 128; st > 0; st >>= 1) {
        if (tid < st) red[tid] += red[tid + st];
        __syncthreads();
    }
    float inv = 1.f / red[0];
    for (int i = tid; i < n; i += 256) row[i] *= inv;
    for (int i = n + tid; i < SEQ; i += 256) row[i] = 0.f;
}

// ---------------- shared swiglu ----------------
__global__ void swiglu_shared_kernel() {
    int t = blockIdx.x;
    for (int i = threadIdx.x; i < IDIM; i += 256) {
        float a = g_gu[(size_t)t * 6144 + i];
        float b = g_gu[(size_t)t * 6144 + 3072 + i];
        g_hs[(size_t)t * 3072 + i] = a * (b / (1.f + __expf(-b)));
    }
}

// ---------------- gate softmax + top-8 ----------------
__global__ void topk_kernel() {
    int t = blockIdx.x;
    int tid = threadIdx.x;
    __shared__ float gate[NEXP];
    __shared__ float red[NEXP];
    float lg = g_logits[t * NEXP + tid];
    red[tid] = lg; __syncthreads();
    for (int st = 32; st > 0; st >>= 1) {
        if (tid < st) red[tid] = fmaxf(red[tid], red[tid + st]);
        __syncthreads();
    }
    float m = red[0]; __syncthreads();
    float e = __expf(lg - m);
    gate[tid] = e;
    red[tid] = e; __syncthreads();
    for (int st = 32; st > 0; st >>= 1) {
        if (tid < st) red[tid] += red[tid + st];
        __syncthreads();
    }
    float inv = 1.f / red[0];
    __syncthreads();
    gate[tid] = e * inv;
    __syncthreads();
    if (tid == 0) {
        float vals[TOPK];
        int idxs[TOPK];
        float den = 0.f;
        for (int k = 0; k < TOPK; k++) {
            float bv = -INFINITY; int bi = 0;
            for (int i = 0; i < NEXP; i++) {
                float v = gate[i];
                if (v > bv) { bv = v; bi = i; }
            }
            vals[k] = bv; idxs[k] = bi; den += bv;
            gate[bi] = -INFINITY;
        }
        den = fmaxf(den, 1.19209290e-07f);
        for (int k = 0; k < TOPK; k++) {
            g_assign_e[t * TOPK + k] = idxs[k];
            g_assign_w[t * TOPK + k] = vals[k] / den;
        }
    }
}

// ---------------- routing ----------------
__global__ void route_kernel() {
    int e = threadIdx.x;
    int cnt = 0;
    for (int i = 0; i < SEQ * TOPK; i++) {
        if (g_assign_e[i] == e) {
            g_assign_p[i] = cnt;
            if (cnt < CAP) g_slot_token[e * CAP + cnt] = i >> 3;
            cnt++;
        }
    }
    g_count[e] = cnt < CAP ? cnt : CAP;
}

// ---------------- expert swiglu ----------------
__global__ void swiglu_expert_kernel() {
    int t = blockIdx.x;
    int e = t >> 2;
    int slot0 = (t & 3) * 128 + blockIdx.y * 16;
    int cnt = g_count[e];
    if (slot0 >= cnt) return;
    int send = slot0 + 16;
    if (send > cnt) send = cnt;
    for (int slot = slot0; slot < send; slot++) {
        size_t r = (size_t)e * CAP + slot;
        for (int i = threadIdx.x; i < IDIM; i += 256) {
            float a = g_gue[r * 6144 + i];
            float b = g_gue[r * 6144 + 3072 + i];
            g_hexp[r * 3072 + i] = a * (b / (1.f + __expf(-b)));
        }
    }
}

// ---------------- final combine ----------------
__global__ void combine_kernel(float* __restrict__ out) {
    int t = blockIdx.x;
    int tid = threadIdx.x;
    __shared__ float w[TOPK];
    __shared__ int rr[TOPK];
    if (tid < TOPK) {
        int i = t * TOPK + tid;
        int p = g_assign_p[i];
        int e = g_assign_e[i];
        bool valid = p < CAP;
        w[tid] = valid ? g_assign_w[i] : 0.f;
        rr[tid] = e * CAP + (valid ? p : 0);
    }
    __syncthreads();
    for (int h = tid; h < HDIM; h += 256) {
        float v = g_h1[(size_t)t * HDIM + h] + g_sharedo[(size_t)t * HDIM + h];
#pragma unroll
        for (int k = 0; k < TOPK; k++) v += w[k] * g_ye[(size_t)rr[k] * HDIM + h];
        out[(size_t)t * HDIM + h] = v;
    }
}

// ---------------- launch ----------------
extern "C" void kernel_launch(void* const* d_in, const int* in_sizes, int n_in,
                              void* d_out, int out_size) {
    const float* hidden = (const float*)d_in[0];
    const float* cosb = (const float*)d_in[1];
    const float* sinb = (const float*)d_in[2];
    const float* ln1_w = (const float*)d_in[3];
    const float* ln2_w = (const float*)d_in[4];
    const float* Wqkv = (const float*)d_in[5];
    const float* Wo = (const float*)d_in[6];
    const float* qnorm_w = (const float*)d_in[7];
    const float* knorm_w = (const float*)d_in[8];
    const float* Wgu_sh = (const float*)d_in[9];
    const float* Wd_sh = (const float*)d_in[10];
    const float* Wgate = (const float*)d_in[11];
    const float* Wgu_ex = (const float*)d_in[12];
    const float* Wd_ex = (const float*)d_in[13];
    float* out = (float*)d_out;

    float *px, *pqkv, *pq, *pkT, *pv, *pscores, *pattn, *ph1, *px2, *pgu, *phs, *psh, *plog;
    float *pgue, *phexp, *pye;
    cudaGetSymbolAddress((void**)&px, g_x);
    cudaGetSymbolAddress((void**)&pqkv, g_qkv);
    cudaGetSymbolAddress((void**)&pq, g_q);
    cudaGetSymbolAddress((void**)&pkT, g_kT);
    cudaGetSymbolAddress((void**)&pv, g_v);
    cudaGetSymbolAddress((void**)&pscores, g_scores);
    cudaGetSymbolAddress((void**)&pattn, g_attn);
    cudaGetSymbolAddress((void**)&ph1, g_h1);
    cudaGetSymbolAddress((void**)&px2, g_x2);
    cudaGetSymbolAddress((void**)&pgu, g_gu);
    cudaGetSymbolAddress((void**)&phs, g_hs);
    cudaGetSymbolAddress((void**)&psh, g_sharedo);
    cudaGetSymbolAddress((void**)&plog, g_logits);
    cudaGetSymbolAddress((void**)&pgue, g_gue);
    cudaGetSymbolAddress((void**)&phexp, g_hexp);
    cudaGetSymbolAddress((void**)&pye, g_ye);

    // 1. x = rmsnorm(hidden, ln1)
    rmsnorm_kernel<<<SEQ, 256>>>(hidden, ln1_w, px);
    // 2. qkv = x @ Wqkv
    bf_gemm<0, false><<<dim3(16, 8), 256>>>(px, Wqkv, pqkv, nullptr, 2048, 1024);
    // 3. rope + qknorm + split
    rope_qk_kernel<<<dim3(SEQ, KVHEADS), 128>>>(cosb, sinb, qnorm_w, knorm_w);
    // 4. scores = q @ k^T (causal block-skip)
    sgemm_kernel<false, 1><<<dim3(8, 8, NHEADS), 256>>>(pq, pkT, pscores, nullptr,
        1024, 1024, 64, 64, 1024, 1024, 65536, 65536, 1048576, 2);
    // 5. causal softmax
    softmax_kernel<<<dim3(SEQ, NHEADS), 256>>>();
    // 6. attn = P @ V (K capped per row-block)
    sgemm_kernel<false, 2><<<dim3(1, 8, NHEADS), 256>>>(pscores, pv, pattn, nullptr,
        1024, 64, 1024, 1024, 64, 1024, 1048576, 65536, 64, 2);
    // 7. h1 = attn @ Wo + hidden
    bf_gemm<0, true><<<dim3(8, 8), 256>>>(pattn, Wo, ph1, hidden, 1024, 1024);
    // 8. x2 = rmsnorm(h1, ln2)
    rmsnorm_kernel<<<SEQ, 256>>>(ph1, ln2_w, px2);
    // 9. gu = x2 @ Wgu_shared
    bf_gemm<0, false><<<dim3(48, 8), 256>>>(px2, Wgu_sh, pgu, nullptr, 6144, 1024);
    // 10. swiglu
    swiglu_shared_kernel<<<SEQ, 256>>>();
    // 11. shared = hs @ Wd_shared
    bf_gemm<0, false><<<dim3(8, 8), 256>>>(phs, Wd_sh, psh, nullptr, 1024, 3072);
    // 12. logits = x2 @ Wgate
    sgemm_kernel<false, 0><<<dim3(1, 8, 1), 256>>>(px2, Wgate, plog, nullptr,
        1024, 64, 1024, 1024, 64, 64, 0, 0, 0, 1);
    // 13. softmax + top8
    topk_kernel<<<SEQ, 64>>>();
    // 14. routing
    route_kernel<<<1, 64>>>();
    // 15. expert GEMM1 (gathered) -> gu_e
    bf_gemm<1, false><<<dim3(48, 256), 256>>>(px2, Wgu_ex, pgue, nullptr, 6144, 1024);
    // 16. expert swiglu
    swiglu_expert_kernel<<<dim3(256, 8), 256>>>();
    // 17. expert GEMM2 -> ye
    bf_gemm<2, false><<<dim3(8, 256), 256>>>(phexp, Wd_ex, pye, nullptr, 1024, 3072);
    // 18. out = h1 + shared + moe
    combine_kernel<<<SEQ, 256>>>(out);
}

// round 4
// speedup vs baseline: 2.2158x; 1.2819x over previous
#include <cuda_runtime.h>
#include <cuda_bf16.h>
#include <math.h>
#include <stdint.h>

#define SEQ 1024
#define HDIM 1024
#define NHEADS 16
#define KVHEADS 8
#define HSZ 64
#define NEXP 64
#define TOPK 8
#define CAP 512
#define IDIM 3072
#define EPSF 1e-6f

// ---------------- scratch ----------------
__device__ float g_x[SEQ * HDIM];
__device__ float g_qkv[SEQ * 2048];
__device__ float g_q[NHEADS * SEQ * HSZ];
__device__ float g_kT[KVHEADS * HSZ * SEQ];
__device__ float g_v[KVHEADS * SEQ * HSZ];
__device__ float g_scores[(size_t)NHEADS * SEQ * SEQ];
__device__ float g_attn[SEQ * HDIM];
__device__ float g_h1[SEQ * HDIM];
__device__ float g_x2[SEQ * HDIM];
__device__ float g_gu[SEQ * 2 * IDIM];
__device__ float g_hs[SEQ * IDIM];
__device__ float g_sharedo[SEQ * HDIM];
__device__ float g_logits[SEQ * NEXP];
__device__ int   g_assign_e[SEQ * TOPK];
__device__ float g_assign_w[SEQ * TOPK];
__device__ int   g_assign_p[SEQ * TOPK];
__device__ int   g_slot_token[NEXP * CAP];
__device__ int   g_count[NEXP];
__device__ float g_gue[(size_t)NEXP * CAP * 2 * IDIM];
__device__ float g_hexp[(size_t)NEXP * CAP * IDIM];
__device__ float g_ye[(size_t)NEXP * CAP * HDIM];

// ---------------- helpers ----------------
__device__ __forceinline__ uint32_t smem_u32(const void* p) {
    uint32_t a;
    asm("{ .reg .u64 t; cvta.to.shared.u64 t, %1; cvt.u32.u64 %0, t; }" : "=r"(a) : "l"(p));
    return a;
}
__device__ __forceinline__ uint32_t packbf(float a, float b) {
    __nv_bfloat162 t = __floats2bfloat162_rn(a, b);
    return *reinterpret_cast<uint32_t*>(&t);
}
__device__ __forceinline__ void split4(float4 v, uint2& h, uint2& l) {
    float hx = __bfloat162float(__float2bfloat16(v.x));
    float hy = __bfloat162float(__float2bfloat16(v.y));
    float hz = __bfloat162float(__float2bfloat16(v.z));
    float hw = __bfloat162float(__float2bfloat16(v.w));
    h.x = packbf(hx, hy);
    h.y = packbf(hz, hw);
    l.x = packbf(v.x - hx, v.y - hy);
    l.y = packbf(v.z - hz, v.w - hw);
}
__device__ __forceinline__ void ldmx4(uint32_t* r, uint32_t addr) {
    asm volatile("ldmatrix.sync.aligned.m8n8.x4.shared.b16 {%0,%1,%2,%3}, [%4];"
                 : "=r"(r[0]), "=r"(r[1]), "=r"(r[2]), "=r"(r[3]) : "r"(addr));
}
__device__ __forceinline__ void ldmx2t(uint32_t* r, uint32_t addr) {
    asm volatile("ldmatrix.sync.aligned.m8n8.x2.trans.shared.b16 {%0,%1}, [%2];"
                 : "=r"(r[0]), "=r"(r[1]) : "r"(addr));
}
__device__ __forceinline__ void mma16816(float* d, const uint32_t* a, const uint32_t* b) {
    asm volatile("mma.sync.aligned.m16n8k16.row.col.f32.bf16.bf16.f32 "
                 "{%0,%1,%2,%3}, {%4,%5,%6,%7}, {%8,%9}, {%0,%1,%2,%3};"
                 : "+f"(d[0]), "+f"(d[1]), "+f"(d[2]), "+f"(d[3])
                 : "r"(a[0]), "r"(a[1]), "r"(a[2]), "r"(a[3]), "r"(b[0]), "r"(b[1]));
}

// ---------------- bf16 split-precision HMMA GEMM, double-buffered ----------------
// C[M,N] = A[M,K] @ B[K,N], fp32-equivalent (hi/lo bf16 split, 3 MMA passes).
// 128x128 tile, BK=32, 256 threads. MODE 0: dense; 1: expert+gather; 2: expert direct.
#define APAD 40
#define BPAD 136
#define A_ELEMS (128 * APAD)
#define B_ELEMS (32 * BPAD)
// smem element offsets (bf16 units)
#define OFF_AH 0
#define OFF_AL (OFF_AH + 2 * A_ELEMS)
#define OFF_BH (OFF_AL + 2 * A_ELEMS)
#define OFF_BL (OFF_BH + 2 * B_ELEMS)
#define SMEM_ELEMS (OFF_BL + 2 * B_ELEMS)
#define SMEM_BYTES (SMEM_ELEMS * 2)

template <int MODE, bool RES>
__global__ void __launch_bounds__(256, 1) bf_gemm(const float* __restrict__ A,
                                                  const float* __restrict__ B,
                                                  float* __restrict__ C,
                                                  const float* __restrict__ res,
                                                  int N, int K) {
    extern __shared__ __align__(16) __nv_bfloat16 sm[];
    int tid = threadIdx.x, lane = tid & 31, wid = tid >> 5;
    int wm = wid & 1, wn = wid >> 1;

    int e = 0, slot0 = 0, cnt = 128;
    size_t crow0;
    if (MODE == 0) {
        crow0 = (size_t)blockIdx.y * 128;
    } else {
        int t = blockIdx.y;
        e = t >> 2;
        slot0 = (t & 3) * 128;
        int c = g_count[e] - slot0;
        if (c <= 0) return;
        cnt = c < 128 ? c : 128;
        B += (size_t)e * K * N;
        crow0 = (size_t)e * CAP + slot0;
    }
    int n0 = blockIdx.x * 128;

    // per-thread load coordinates
    int a_row = tid >> 1;                 // 2 threads per row
    int a_q = (tid & 1) * 16;             // starting float within row (handles 16 floats = 4 float4)
    int b_row = tid >> 3;                 // 8 threads per k-row (32 rows)
    int b_q = (tid & 7) * 16;             // 16 floats each

    const float* aptr;
    bool aok = a_row < cnt;
    if (MODE == 1) {
        int tok = aok ? g_slot_token[e * CAP + slot0 + a_row] : 0;
        aptr = A + (size_t)tok * K + a_q;
    } else {
        aptr = A + (crow0 + a_row) * (size_t)K + a_q;
    }
    const float* bptr = B + (size_t)b_row * N + n0 + b_q;

    float acc[4][4][4];
#pragma unroll
    for (int i = 0; i < 4; i++)
#pragma unroll
        for (int j = 0; j < 4; j++)
#pragma unroll
            for (int v = 0; v < 4; v++) acc[i][j][v] = 0.f;

    uint32_t sbase = smem_u32(sm);

    float4 pa[4], pb[4];
    // prologue: load chunk 0
#pragma unroll
    for (int j = 0; j < 4; j++)
        pa[j] = aok ? *(const float4*)(aptr + j * 4) : make_float4(0.f, 0.f, 0.f, 0.f);
#pragma unroll
    for (int j = 0; j < 4; j++)
        pb[j] = *(const float4*)(bptr + j * 4);

    // store chunk 0 into buffer 0
    {
        __nv_bfloat16* AH = sm + OFF_AH;
        __nv_bfloat16* AL = sm + OFF_AL;
        __nv_bfloat16* BH = sm + OFF_BH;
        __nv_bfloat16* BL = sm + OFF_BL;
#pragma unroll
        for (int j = 0; j < 4; j++) {
            uint2 h, l;
            split4(pa[j], h, l);
            int o = a_row * APAD + a_q + j * 4;
            *(uint2*)(AH + o) = h;
            *(uint2*)(AL + o) = l;
        }
#pragma unroll
        for (int j = 0; j < 4; j++) {
            uint2 h, l;
            split4(pb[j], h, l);
            int o = b_row * BPAD + b_q + j * 4;
            *(uint2*)(BH + o) = h;
            *(uint2*)(BL + o) = l;
        }
    }
    __syncthreads();

    int nk = K >> 5;
    for (int c = 0; c < nk; c++) {
        int cur = c & 1;
        bool more = (c + 1) < nk;
        // issue next chunk's gmem loads early
        if (more) {
            int k1 = (c + 1) << 5;
#pragma unroll
            for (int j = 0; j < 4; j++)
                pa[j] = aok ? *(const float4*)(aptr + k1 + j * 4) : make_float4(0.f, 0.f, 0.f, 0.f);
#pragma unroll
            for (int j = 0; j < 4; j++)
                pb[j] = *(const float4*)(bptr + (size_t)k1 * N + j * 4);
        }

        // MMA on current buffer
        uint32_t aho = sbase + (OFF_AH + cur * A_ELEMS) * 2;
        uint32_t alo = sbase + (OFF_AL + cur * A_ELEMS) * 2;
        uint32_t bho = sbase + (OFF_BH + cur * B_ELEMS) * 2;
        uint32_t blo = sbase + (OFF_BL + cur * B_ELEMS) * 2;
#pragma unroll
        for (int ks = 0; ks < 2; ks++) {
            uint32_t ah[4][4], al[4][4], bh[4][2], bl[4][2];
#pragma unroll
            for (int i = 0; i < 4; i++) {
                uint32_t off = ((wm * 64 + i * 16 + (lane & 15)) * APAD + ks * 16 + (lane >> 4) * 8) * 2;
                ldmx4(ah[i], aho + off);
                ldmx4(al[i], alo + off);
            }
#pragma unroll
            for (int j = 0; j < 4; j++) {
                uint32_t off = ((ks * 16 + (lane & 15)) * BPAD + wn * 32 + j * 8) * 2;
                ldmx2t(bh[j], bho + off);
                ldmx2t(bl[j], blo + off);
            }
#pragma unroll
            for (int i = 0; i < 4; i++)
#pragma unroll
                for (int j = 0; j < 4; j++) {
                    mma16816(acc[i][j], ah[i], bh[j]);
                    mma16816(acc[i][j], al[i], bh[j]);
                    mma16816(acc[i][j], ah[i], bl[j]);
                }
        }

        // convert + store next chunk into alternate buffer
        if (more) {
            int nxt = cur ^ 1;
            __nv_bfloat16* AH = sm + OFF_AH + nxt * A_ELEMS;
            __nv_bfloat16* AL = sm + OFF_AL + nxt * A_ELEMS;
            __nv_bfloat16* BH = sm + OFF_BH + nxt * B_ELEMS;
            __nv_bfloat16* BL = sm + OFF_BL + nxt * B_ELEMS;
#pragma unroll
            for (int j = 0; j < 4; j++) {
                uint2 h, l;
                split4(pa[j], h, l);
                int o = a_row * APAD + a_q + j * 4;
                *(uint2*)(AH + o) = h;
                *(uint2*)(AL + o) = l;
            }
#pragma unroll
            for (int j = 0; j < 4; j++) {
                uint2 h, l;
                split4(pb[j], h, l);
                int o = b_row * BPAD + b_q + j * 4;
                *(uint2*)(BH + o) = h;
                *(uint2*)(BL + o) = l;
            }
        }
        __syncthreads();
    }

    // ---- epilogue ----
#pragma unroll
    for (int i = 0; i < 4; i++) {
        int r0 = wm * 64 + i * 16 + (lane >> 2);
#pragma unroll
        for (int j = 0; j < 4; j++) {
            int c0 = n0 + wn * 32 + j * 8 + (lane & 3) * 2;
            float* cp = C + (crow0 + r0) * (size_t)N + c0;
            float* cp2 = C + (crow0 + r0 + 8) * (size_t)N + c0;
            if (RES) {
                const float* rp = res + (crow0 + r0) * (size_t)N + c0;
                const float* rp2 = res + (crow0 + r0 + 8) * (size_t)N + c0;
                cp[0] = acc[i][j][0] + rp[0];
                cp[1] = acc[i][j][1] + rp[1];
                cp2[0] = acc[i][j][2] + rp2[0];
                cp2[1] = acc[i][j][3] + rp2[1];
            } else {
                cp[0] = acc[i][j][0];
                cp[1] = acc[i][j][1];
                cp2[0] = acc[i][j][2];
                cp2[1] = acc[i][j][3];
            }
        }
    }
}

// ---------------- rmsnorm ----------------
__global__ void rmsnorm_kernel(const float* __restrict__ in, const float* __restrict__ w,
                               float* __restrict__ out) {
    int row = blockIdx.x;
    const float* x = in + (size_t)row * HDIM;
    float* o = out + (size_t)row * HDIM;
    __shared__ float red[256];
    float s = 0.f;
    for (int i = threadIdx.x; i < HDIM; i += 256) { float v = x[i]; s += v * v; }
    red[threadIdx.x] = s; __syncthreads();
    for (int st = 128; st > 0; st >>= 1) {
        if (threadIdx.x < st) red[threadIdx.x] += red[threadIdx.x + st];
        __syncthreads();
    }
    float inv = rsqrtf(red[0] / (float)HDIM + EPSF);
    for (int i = threadIdx.x; i < HDIM; i += 256) o[i] = w[i] * x[i] * inv;
}

// ---------------- fp32 SGEMM (attention + logits) ----------------
template <bool RES, int KM>
__global__ void sgemm_kernel(const float* __restrict__ A, const float* __restrict__ B,
                             float* __restrict__ C, const float* __restrict__ res,
                             int M, int N, int K, int lda, int ldb, int ldc,
                             long sA, long sB, long sC, int bdiv) {
    int z = blockIdx.z;
    int row0 = blockIdx.y * 128, col0 = blockIdx.x * 128;
    if (KM == 1 && col0 > row0) return;
    int Keff = K;
    if (KM == 2) Keff = (row0 + 128 < K) ? row0 + 128 : K;
    A += (size_t)z * sA;
    B += (size_t)(z / bdiv) * sB;
    C += (size_t)z * sC;
    if (RES) res += (size_t)z * sC;
    __shared__ float As[8][128];
    __shared__ float Bs[8][128];
    int tid = threadIdx.x;
    int tx = tid & 15, ty = tid >> 4;
    int arow = tid >> 1;
    int acol = (tid & 1) * 4;
    int brow = tid >> 5;
    int bcol = (tid & 31) * 4;
    const float* Aptr = A + (size_t)(row0 + arow) * lda + acol;
    const float* Bptr = B + (size_t)brow * ldb + col0 + bcol;
    bool bok = (col0 + bcol) < N;
    float acc[8][8];
#pragma unroll
    for (int i = 0; i < 8; i++)
#pragma unroll
        for (int j = 0; j < 8; j++) acc[i][j] = 0.f;

    for (int k0 = 0; k0 < Keff; k0 += 8) {
        float4 av = *(const float4*)(Aptr + k0);
        As[acol + 0][arow] = av.x;
        As[acol + 1][arow] = av.y;
        As[acol + 2][arow] = av.z;
        As[acol + 3][arow] = av.w;
        float4 bv = make_float4(0.f, 0.f, 0.f, 0.f);
        if (bok) bv = *(const float4*)(Bptr + (size_t)k0 * ldb);
        *(float4*)&Bs[brow][bcol] = bv;
        __syncthreads();
#pragma unroll
        for (int kk = 0; kk < 8; kk++) {
            float am[8], bn[8];
#pragma unroll
            for (int i = 0; i < 8; i++) am[i] = As[kk][ty * 8 + i];
#pragma unroll
            for (int j = 0; j < 8; j++) bn[j] = Bs[kk][tx * 8 + j];
#pragma unroll
            for (int i = 0; i < 8; i++)
#pragma unroll
                for (int j = 0; j < 8; j++) acc[i][j] += am[i] * bn[j];
        }
        __syncthreads();
    }
#pragma unroll
    for (int i = 0; i < 8; i++) {
        int r = row0 + ty * 8 + i;
#pragma unroll
        for (int j = 0; j < 8; j++) {
            int c = col0 + tx * 8 + j;
            if (c < N) {
                float v = acc[i][j];
                if (RES) v += res[(size_t)r * ldc + c];
                C[(size_t)r * ldc + c] = v;
            }
        }
    }
}

// ---------------- RoPE + qk rmsnorm + layout split ----------------
__global__ void rope_qk_kernel(const float* __restrict__ cosb, const float* __restrict__ sinb,
                               const float* __restrict__ qw, const float* __restrict__ kw) {
    int s = blockIdx.x, kv = blockIdx.y;
    int w = threadIdx.x >> 5, lane = threadIdx.x & 31;
    const float* src = g_qkv + (size_t)s * 2048 + kv * 256 + w * 64;
    float x1 = src[lane], x2 = src[lane + 32];
    float o1, o2;
    if (w < 3) {
        float c1 = cosb[s * 64 + lane], s1 = sinb[s * 64 + lane];
        float c2 = cosb[s * 64 + lane + 32], s2 = sinb[s * 64 + lane + 32];
        o1 = x1 * c1 - x2 * s1;
        o2 = x2 * c2 + x1 * s2;
        float ss = o1 * o1 + o2 * o2;
#pragma unroll
        for (int off = 16; off; off >>= 1) ss += __shfl_xor_sync(0xffffffffu, ss, off);
        float inv = rsqrtf(ss / 64.f + EPSF);
        const float* wt = (w < 2) ? qw : kw;
        o1 *= inv * wt[lane];
        o2 *= inv * wt[lane + 32];
    } else {
        o1 = x1; o2 = x2;
    }
    if (w < 2) {
        int head = kv * 2 + w;
        g_q[(size_t)head * 65536 + s * 64 + lane] = o1;
        g_q[(size_t)head * 65536 + s * 64 + lane + 32] = o2;
    } else if (w == 2) {
        g_kT[(size_t)kv * 65536 + lane * 1024 + s] = o1;
        g_kT[(size_t)kv * 65536 + (lane + 32) * 1024 + s] = o2;
    } else {
        g_v[(size_t)kv * 65536 + s * 64 + lane] = o1;
        g_v[(size_t)kv * 65536 + s * 64 + lane + 32] = o2;
    }
}

// ---------------- causal scaled softmax ----------------
__global__ void softmax_kernel() {
    int s = blockIdx.x, h = blockIdx.y;
    float* row = g_scores + ((size_t)h * SEQ + s) * SEQ;
    int n = s + 1;
    __shared__ float red[256];
    int tid = threadIdx.x;
    float m = -INFINITY;
    for (int i = tid; i < n; i += 256) m = fmaxf(m, row[i] * 0.125f);
    red[tid] = m; __syncthreads();
    for (int st = 128; st > 0; st >>= 1) {
        if (tid < st) red[tid] = fmaxf(red[tid], red[tid + st]);
        __syncthreads();
    }
    m = red[0]; __syncthreads();
    float sum = 0.f;
    for (int i = tid; i < n; i += 256) {
        float p = __expf(row[i] * 0.125f - m);
        row[i] = p;
        sum += p;
    }
    red[tid] = sum; __syncthreads();
    for (int st = 128; st > 0; st >>= 1) {
        if (tid < st) red[tid] += red[tid + st];
        __syncthreads();
    }
    float inv = 1.f / red[0];
    for (int i = tid; i < n; i += 256) row[i] *= inv;
    for (int i = n + tid; i < SEQ; i += 256) row[i] = 0.f;
}

// ---------------- shared swiglu ----------------
__global__ void swiglu_shared_kernel() {
    int t = blockIdx.x;
    for (int i = threadIdx.x; i < IDIM; i += 256) {
        float a = g_gu[(size_t)t * 6144 + i];
        float b = g_gu[(size_t)t * 6144 + 3072 + i];
        g_hs[(size_t)t * 3072 + i] = a * (b / (1.f + __expf(-b)));
    }
}

// ---------------- gate softmax + top-8 ----------------
__global__ void topk_kernel() {
    int t = blockIdx.x;
    int tid = threadIdx.x;
    __shared__ float gate[NEXP];
    __shared__ float red[NEXP];
    float lg = g_logits[t * NEXP + tid];
    red[tid] = lg; __syncthreads();
    for (int st = 32; st > 0; st >>= 1) {
        if (tid < st) red[tid] = fmaxf(red[tid], red[tid + st]);
        __syncthreads();
    }
    float m = red[0]; __syncthreads();
    float e = __expf(lg - m);
    gate[tid] = e;
    red[tid] = e; __syncthreads();
    for (int st = 32; st > 0; st >>= 1) {
        if (tid < st) red[tid] += red[tid + st];
        __syncthreads();
    }
    float inv = 1.f / red[0];
    __syncthreads();
    gate[tid] = e * inv;
    __syncthreads();
    if (tid == 0) {
        float vals[TOPK];
        int idxs[TOPK];
        float den = 0.f;
        for (int k = 0; k < TOPK; k++) {
            float bv = -INFINITY; int bi = 0;
            for (int i = 0; i < NEXP; i++) {
                float v = gate[i];
                if (v > bv) { bv = v; bi = i; }
            }
            vals[k] = bv; idxs[k] = bi; den += bv;
            gate[bi] = -INFINITY;
        }
        den = fmaxf(den, 1.19209290e-07f);
        for (int k = 0; k < TOPK; k++) {
            g_assign_e[t * TOPK + k] = idxs[k];
            g_assign_w[t * TOPK + k] = vals[k] / den;
        }
    }
}

// ---------------- routing ----------------
__global__ void route_kernel() {
    int e = threadIdx.x;
    int cnt = 0;
    for (int i = 0; i < SEQ * TOPK; i++) {
        if (g_assign_e[i] == e) {
            g_assign_p[i] = cnt;
            if (cnt < CAP) g_slot_token[e * CAP + cnt] = i >> 3;
            cnt++;
        }
    }
    g_count[e] = cnt < CAP ? cnt : CAP;
}

// ---------------- expert swiglu ----------------
__global__ void swiglu_expert_kernel() {
    int t = blockIdx.x;
    int e = t >> 2;
    int slot0 = (t & 3) * 128 + blockIdx.y * 16;
    int cnt = g_count[e];
    if (slot0 >= cnt) return;
    int send = slot0 + 16;
    if (send > cnt) send = cnt;
    for (int slot = slot0; slot < send; slot++) {
        size_t r = (size_t)e * CAP + slot;
        for (int i = threadIdx.x; i < IDIM; i += 256) {
            float a = g_gue[r * 6144 + i];
            float b = g_gue[r * 6144 + 3072 + i];
            g_hexp[r * 3072 + i] = a * (b / (1.f + __expf(-b)));
        }
    }
}

// ---------------- final combine ----------------
__global__ void combine_kernel(float* __restrict__ out) {
    int t = blockIdx.x;
    int tid = threadIdx.x;
    __shared__ float w[TOPK];
    __shared__ int rr[TOPK];
    if (tid < TOPK) {
        int i = t * TOPK + tid;
        int p = g_assign_p[i];
        int e = g_assign_e[i];
        bool valid = p < CAP;
        w[tid] = valid ? g_assign_w[i] : 0.f;
        rr[tid] = e * CAP + (valid ? p : 0);
    }
    __syncthreads();
    for (int h = tid; h < HDIM; h += 256) {
        float v = g_h1[(size_t)t * HDIM + h] + g_sharedo[(size_t)t * HDIM + h];
#pragma unroll
        for (int k = 0; k < TOPK; k++) v += w[k] * g_ye[(size_t)rr[k] * HDIM + h];
        out[(size_t)t * HDIM + h] = v;
    }
}

// ---------------- launch ----------------
extern "C" void kernel_launch(void* const* d_in, const int* in_sizes, int n_in,
                              void* d_out, int out_size) {
    const float* hidden = (const float*)d_in[0];
    const float* cosb = (const float*)d_in[1];
    const float* sinb = (const float*)d_in[2];
    const float* ln1_w = (const float*)d_in[3];
    const float* ln2_w = (const float*)d_in[4];
    const float* Wqkv = (const float*)d_in[5];
    const float* Wo = (const float*)d_in[6];
    const float* qnorm_w = (const float*)d_in[7];
    const float* knorm_w = (const float*)d_in[8];
    const float* Wgu_sh = (const float*)d_in[9];
    const float* Wd_sh = (const float*)d_in[10];
    const float* Wgate = (const float*)d_in[11];
    const float* Wgu_ex = (const float*)d_in[12];
    const float* Wd_ex = (const float*)d_in[13];
    float* out = (float*)d_out;

    float *px, *pqkv, *pq, *pkT, *pv, *pscores, *pattn, *ph1, *px2, *pgu, *phs, *psh, *plog;
    float *pgue, *phexp, *pye;
    cudaGetSymbolAddress((void**)&px, g_x);
    cudaGetSymbolAddress((void**)&pqkv, g_qkv);
    cudaGetSymbolAddress((void**)&pq, g_q);
    cudaGetSymbolAddress((void**)&pkT, g_kT);
    cudaGetSymbolAddress((void**)&pv, g_v);
    cudaGetSymbolAddress((void**)&pscores, g_scores);
    cudaGetSymbolAddress((void**)&pattn, g_attn);
    cudaGetSymbolAddress((void**)&ph1, g_h1);
    cudaGetSymbolAddress((void**)&px2, g_x2);
    cudaGetSymbolAddress((void**)&pgu, g_gu);
    cudaGetSymbolAddress((void**)&phs, g_hs);
    cudaGetSymbolAddress((void**)&psh, g_sharedo);
    cudaGetSymbolAddress((void**)&plog, g_logits);
    cudaGetSymbolAddress((void**)&pgue, g_gue);
    cudaGetSymbolAddress((void**)&phexp, g_hexp);
    cudaGetSymbolAddress((void**)&pye, g_ye);

    static int attr_done = 0;
    if (!attr_done) {
        cudaFuncSetAttribute(bf_gemm<0, false>, cudaFuncAttributeMaxDynamicSharedMemorySize, SMEM_BYTES);
        cudaFuncSetAttribute(bf_gemm<0, true>, cudaFuncAttributeMaxDynamicSharedMemorySize, SMEM_BYTES);
        cudaFuncSetAttribute(bf_gemm<1, false>, cudaFuncAttributeMaxDynamicSharedMemorySize, SMEM_BYTES);
        cudaFuncSetAttribute(bf_gemm<2, false>, cudaFuncAttributeMaxDynamicSharedMemorySize, SMEM_BYTES);
        attr_done = 1;
    }

    // 1. x = rmsnorm(hidden, ln1)
    rmsnorm_kernel<<<SEQ, 256>>>(hidden, ln1_w, px);
    // 2. qkv = x @ Wqkv
    bf_gemm<0, false><<<dim3(16, 8), 256, SMEM_BYTES>>>(px, Wqkv, pqkv, nullptr, 2048, 1024);
    // 3. rope + qknorm + split
    rope_qk_kernel<<<dim3(SEQ, KVHEADS), 128>>>(cosb, sinb, qnorm_w, knorm_w);
    // 4. scores = q @ k^T (causal block-skip)
    sgemm_kernel<false, 1><<<dim3(8, 8, NHEADS), 256>>>(pq, pkT, pscores, nullptr,
        1024, 1024, 64, 64, 1024, 1024, 65536, 65536, 1048576, 2);
    // 5. causal softmax
    softmax_kernel<<<dim3(SEQ, NHEADS), 256>>>();
    // 6. attn = P @ V (K capped per row-block)
    sgemm_kernel<false, 2><<<dim3(1, 8, NHEADS), 256>>>(pscores, pv, pattn, nullptr,
        1024, 64, 1024, 1024, 64, 1024, 1048576, 65536, 64, 2);
    // 7. h1 = attn @ Wo + hidden
    bf_gemm<0, true><<<dim3(8, 8), 256, SMEM_BYTES>>>(pattn, Wo, ph1, hidden, 1024, 1024);
    // 8. x2 = rmsnorm(h1, ln2)
    rmsnorm_kernel<<<SEQ, 256>>>(ph1, ln2_w, px2);
    // 9. gu = x2 @ Wgu_shared
    bf_gemm<0, false><<<dim3(48, 8), 256, SMEM_BYTES>>>(px2, Wgu_sh, pgu, nullptr, 6144, 1024);
    // 10. swiglu
    swiglu_shared_kernel<<<SEQ, 256>>>();
    // 11. shared = hs @ Wd_shared
    bf_gemm<0, false><<<dim3(8, 8), 256, SMEM_BYTES>>>(phs, Wd_sh, psh, nullptr, 1024, 3072);
    // 12. logits = x2 @ Wgate
    sgemm_kernel<false, 0><<<dim3(1, 8, 1), 256>>>(px2, Wgate, plog, nullptr,
        1024, 64, 1024, 1024, 64, 64, 0, 0, 0, 1);
    // 13. softmax + top8
    topk_kernel<<<SEQ, 64>>>();
    // 14. routing
    route_kernel<<<1, 64>>>();
    // 15. expert GEMM1 (gathered) -> gu_e
    bf_gemm<1, false><<<dim3(48, 256), 256, SMEM_BYTES>>>(px2, Wgu_ex, pgue, nullptr, 6144, 1024);
    // 16. expert swiglu
    swiglu_expert_kernel<<<dim3(256, 8), 256>>>();
    // 17. expert GEMM2 -> ye
    bf_gemm<2, false><<<dim3(8, 256), 256, SMEM_BYTES>>>(phexp, Wd_ex, pye, nullptr, 1024, 3072);
    // 18. out = h1 + shared + moe
    combine_kernel<<<SEQ, 256>>>(out);
}

// round 5
// speedup vs baseline: 2.3142x; 1.0444x over previous
#include <cuda_runtime.h>
#include <cuda_bf16.h>
#include <math.h>
#include <stdint.h>

#define SEQ 1024
#define HDIM 1024
#define NHEADS 16
#define KVHEADS 8
#define HSZ 64
#define NEXP 64
#define TOPK 8
#define CAP 512
#define IDIM 3072
#define EPSF 1e-6f

// ---------------- scratch ----------------
__device__ __nv_bfloat16 g_x_h[SEQ * HDIM];
__device__ __nv_bfloat16 g_x_l[SEQ * HDIM];
__device__ float g_qkv[SEQ * 2048];
__device__ float g_q[NHEADS * SEQ * HSZ];
__device__ float g_kT[KVHEADS * HSZ * SEQ];
__device__ float g_v[KVHEADS * SEQ * HSZ];
__device__ float g_scores[(size_t)NHEADS * SEQ * SEQ];
__device__ float g_attn[SEQ * HDIM];
__device__ float g_h1[SEQ * HDIM];
__device__ float g_x2[SEQ * HDIM];
__device__ __nv_bfloat16 g_x2_h[SEQ * HDIM];
__device__ __nv_bfloat16 g_x2_l[SEQ * HDIM];
__device__ float g_gu[SEQ * 2 * IDIM];
__device__ __nv_bfloat16 g_hs_h[SEQ * IDIM];
__device__ __nv_bfloat16 g_hs_l[SEQ * IDIM];
__device__ float g_sharedo[SEQ * HDIM];
__device__ float g_logits[SEQ * NEXP];
__device__ int   g_assign_e[SEQ * TOPK];
__device__ float g_assign_w[SEQ * TOPK];
__device__ int   g_assign_p[SEQ * TOPK];
__device__ int   g_slot_token[NEXP * CAP];
__device__ int   g_count[NEXP];
__device__ float g_gue[(size_t)NEXP * CAP * 2 * IDIM];
__device__ __nv_bfloat16 g_hexp_h[(size_t)NEXP * CAP * IDIM];
__device__ __nv_bfloat16 g_hexp_l[(size_t)NEXP * CAP * IDIM];
__device__ float g_ye[(size_t)NEXP * CAP * HDIM];

// ---------------- helpers ----------------
__device__ __forceinline__ uint32_t smem_u32(const void* p) {
    uint32_t a;
    asm("{ .reg .u64 t; cvta.to.shared.u64 t, %1; cvt.u32.u64 %0, t; }" : "=r"(a) : "l"(p));
    return a;
}
__device__ __forceinline__ uint32_t packbf(float a, float b) {
    __nv_bfloat162 t = __floats2bfloat162_rn(a, b);
    return *reinterpret_cast<uint32_t*>(&t);
}
__device__ __forceinline__ void split4(float4 v, uint2& h, uint2& l) {
    float hx = __bfloat162float(__float2bfloat16(v.x));
    float hy = __bfloat162float(__float2bfloat16(v.y));
    float hz = __bfloat162float(__float2bfloat16(v.z));
    float hw = __bfloat162float(__float2bfloat16(v.w));
    h.x = packbf(hx, hy);
    h.y = packbf(hz, hw);
    l.x = packbf(v.x - hx, v.y - hy);
    l.y = packbf(v.z - hz, v.w - hw);
}
__device__ __forceinline__ void splitw(float v, __nv_bfloat16& h, __nv_bfloat16& l) {
    __nv_bfloat16 hh = __float2bfloat16(v);
    h = hh;
    l = __float2bfloat16(v - __bfloat162float(hh));
}
__device__ __forceinline__ void ldmx4(uint32_t* r, uint32_t addr) {
    asm volatile("ldmatrix.sync.aligned.m8n8.x4.shared.b16 {%0,%1,%2,%3}, [%4];"
                 : "=r"(r[0]), "=r"(r[1]), "=r"(r[2]), "=r"(r[3]) : "r"(addr));
}
__device__ __forceinline__ void ldmx2t(uint32_t* r, uint32_t addr) {
    asm volatile("ldmatrix.sync.aligned.m8n8.x2.trans.shared.b16 {%0,%1}, [%2];"
                 : "=r"(r[0]), "=r"(r[1]) : "r"(addr));
}
__device__ __forceinline__ void mma16816(float* d, const uint32_t* a, const uint32_t* b) {
    asm volatile("mma.sync.aligned.m16n8k16.row.col.f32.bf16.bf16.f32 "
                 "{%0,%1,%2,%3}, {%4,%5,%6,%7}, {%8,%9}, {%0,%1,%2,%3};"
                 : "+f"(d[0]), "+f"(d[1]), "+f"(d[2]), "+f"(d[3])
                 : "r"(a[0]), "r"(a[1]), "r"(a[2]), "r"(a[3]), "r"(b[0]), "r"(b[1]));
}

// ---------------- bf16 split-precision HMMA GEMM, double-buffered ----------------
#define APAD 40
#define BPAD 136
#define A_ELEMS (128 * APAD)
#define B_ELEMS (32 * BPAD)
#define OFF_AH 0
#define OFF_AL (OFF_AH + 2 * A_ELEMS)
#define OFF_BH (OFF_AL + 2 * A_ELEMS)
#define OFF_BL (OFF_BH + 2 * B_ELEMS)
#define SMEM_ELEMS (OFF_BL + 2 * B_ELEMS)
#define SMEM_BYTES (SMEM_ELEMS * 2)

// MODE 0: dense; 1: expert+gather; 2: expert direct. ASPLIT: A is pre-split bf16 hi/lo.
template <int MODE, bool RES, bool ASPLIT>
__global__ void __launch_bounds__(256, 1) bf_gemm(const void* __restrict__ Av,
                                                  const __nv_bfloat16* __restrict__ Alp,
                                                  const float* __restrict__ B,
                                                  float* __restrict__ C,
                                                  const float* __restrict__ res,
                                                  int N, int K) {
    extern __shared__ __align__(16) __nv_bfloat16 sm[];
    int tid = threadIdx.x, lane = tid & 31, wid = tid >> 5;
    int wm = wid & 1, wn = wid >> 1;

    int e = 0, slot0 = 0, cnt = 128;
    size_t crow0;
    if (MODE == 0) {
        crow0 = (size_t)blockIdx.y * 128;
    } else {
        int t = blockIdx.y;
        e = t >> 2;
        slot0 = (t & 3) * 128;
        int c = g_count[e] - slot0;
        if (c <= 0) return;
        cnt = c < 128 ? c : 128;
        B += (size_t)e * K * N;
        crow0 = (size_t)e * CAP + slot0;
    }
    int n0 = blockIdx.x * 128;

    int a_row = tid >> 1;
    int a_q = (tid & 1) * 16;
    int b_row = tid >> 3;
    int b_q = (tid & 7) * 16;

    bool aok = a_row < cnt;
    size_t a_off;
    if (MODE == 1) {
        int tok = aok ? g_slot_token[e * CAP + slot0 + a_row] : 0;
        a_off = (size_t)tok * K + a_q;
    } else {
        a_off = (crow0 + a_row) * (size_t)K + a_q;
    }
    const float* aptr_f = (const float*)Av + a_off;
    const __nv_bfloat16* aptr_h = (const __nv_bfloat16*)Av + a_off;
    const __nv_bfloat16* aptr_l = Alp + a_off;
    const float* bptr = B + (size_t)b_row * N + n0 + b_q;

    float acc[4][4][4];
#pragma unroll
    for (int i = 0; i < 4; i++)
#pragma unroll
        for (int j = 0; j < 4; j++)
#pragma unroll
            for (int v = 0; v < 4; v++) acc[i][j][v] = 0.f;

    uint32_t sbase = smem_u32(sm);
    const uint4 z4 = make_uint4(0, 0, 0, 0);

    float4 pa[4];
    uint4 pah[2], pal[2];
    float4 pb[4];

    // prologue: load chunk 0
    if (ASPLIT) {
        pah[0] = aok ? *(const uint4*)(aptr_h) : z4;
        pah[1] = aok ? *(const uint4*)(aptr_h + 8) : z4;
        pal[0] = aok ? *(const uint4*)(aptr_l) : z4;
        pal[1] = aok ? *(const uint4*)(aptr_l + 8) : z4;
    } else {
#pragma unroll
        for (int j = 0; j < 4; j++)
            pa[j] = aok ? *(const float4*)(aptr_f + j * 4) : make_float4(0.f, 0.f, 0.f, 0.f);
    }
#pragma unroll
    for (int j = 0; j < 4; j++)
        pb[j] = *(const float4*)(bptr + j * 4);

    // store chunk 0 into buffer 0
    {
        __nv_bfloat16* AH = sm + OFF_AH;
        __nv_bfloat16* AL = sm + OFF_AL;
        __nv_bfloat16* BH = sm + OFF_BH;
        __nv_bfloat16* BL = sm + OFF_BL;
        if (ASPLIT) {
            int o = a_row * APAD + a_q;
            *(uint4*)(AH + o) = pah[0];
            *(uint4*)(AH + o + 8) = pah[1];
            *(uint4*)(AL + o) = pal[0];
            *(uint4*)(AL + o + 8) = pal[1];
        } else {
#pragma unroll
            for (int j = 0; j < 4; j++) {
                uint2 h, l;
                split4(pa[j], h, l);
                int o = a_row * APAD + a_q + j * 4;
                *(uint2*)(AH + o) = h;
                *(uint2*)(AL + o) = l;
            }
        }
#pragma unroll
        for (int j = 0; j < 4; j++) {
            uint2 h, l;
            split4(pb[j], h, l);
            int o = b_row * BPAD + b_q + j * 4;
            *(uint2*)(BH + o) = h;
            *(uint2*)(BL + o) = l;
        }
    }
    __syncthreads();

    int nk = K >> 5;
    for (int c = 0; c < nk; c++) {
        int cur = c & 1;
        bool more = (c + 1) < nk;
        if (more) {
            int k1 = (c + 1) << 5;
            if (ASPLIT) {
                pah[0] = aok ? *(const uint4*)(aptr_h + k1) : z4;
                pah[1] = aok ? *(const uint4*)(aptr_h + k1 + 8) : z4;
                pal[0] = aok ? *(const uint4*)(aptr_l + k1) : z4;
                pal[1] = aok ? *(const uint4*)(aptr_l + k1 + 8) : z4;
            } else {
#pragma unroll
                for (int j = 0; j < 4; j++)
                    pa[j] = aok ? *(const float4*)(aptr_f + k1 + j * 4) : make_float4(0.f, 0.f, 0.f, 0.f);
            }
#pragma unroll
            for (int j = 0; j < 4; j++)
                pb[j] = *(const float4*)(bptr + (size_t)k1 * N + j * 4);
        }

        uint32_t aho = sbase + (OFF_AH + cur * A_ELEMS) * 2;
        uint32_t alo = sbase + (OFF_AL + cur * A_ELEMS) * 2;
        uint32_t bho = sbase + (OFF_BH + cur * B_ELEMS) * 2;
        uint32_t blo = sbase + (OFF_BL + cur * B_ELEMS) * 2;
#pragma unroll
        for (int ks = 0; ks < 2; ks++) {
            uint32_t ah[4][4], al[4][4], bh[4][2], bl[4][2];
#pragma unroll
            for (int i = 0; i < 4; i++) {
                uint32_t off = ((wm * 64 + i * 16 + (lane & 15)) * APAD + ks * 16 + (lane >> 4) * 8) * 2;
                ldmx4(ah[i], aho + off);
                ldmx4(al[i], alo + off);
            }
#pragma unroll
            for (int j = 0; j < 4; j++) {
                uint32_t off = ((ks * 16 + (lane & 15)) * BPAD + wn * 32 + j * 8) * 2;
                ldmx2t(bh[j], bho + off);
                ldmx2t(bl[j], blo + off);
            }
            // 3 separated passes: no back-to-back RAW on any accumulator
#pragma unroll
            for (int i = 0; i < 4; i++)
#pragma unroll
                for (int j = 0; j < 4; j++) mma16816(acc[i][j], ah[i], bh[j]);
#pragma unroll
            for (int i = 0; i < 4; i++)
#pragma unroll
                for (int j = 0; j < 4; j++) mma16816(acc[i][j], al[i], bh[j]);
#pragma unroll
            for (int i = 0; i < 4; i++)
#pragma unroll
                for (int j = 0; j < 4; j++) mma16816(acc[i][j], ah[i], bl[j]);
        }

        if (more) {
            int nxt = cur ^ 1;
            __nv_bfloat16* AH = sm + OFF_AH + nxt * A_ELEMS;
            __nv_bfloat16* AL = sm + OFF_AL + nxt * A_ELEMS;
            __nv_bfloat16* BH = sm + OFF_BH + nxt * B_ELEMS;
            __nv_bfloat16* BL = sm + OFF_BL + nxt * B_ELEMS;
            if (ASPLIT) {
                int o = a_row * APAD + a_q;
                *(uint4*)(AH + o) = pah[0];
                *(uint4*)(AH + o + 8) = pah[1];
                *(uint4*)(AL + o) = pal[0];
                *(uint4*)(AL + o + 8) = pal[1];
            } else {
#pragma unroll
                for (int j = 0; j < 4; j++) {
                    uint2 h, l;
                    split4(pa[j], h, l);
                    int o = a_row * APAD + a_q + j * 4;
                    *(uint2*)(AH + o) = h;
                    *(uint2*)(AL + o) = l;
                }
            }
#pragma unroll
            for (int j = 0; j < 4; j++) {
                uint2 h, l;
                split4(pb[j], h, l);
                int o = b_row * BPAD + b_q + j * 4;
                *(uint2*)(BH + o) = h;
                *(uint2*)(BL + o) = l;
            }
        }
        __syncthreads();
    }

    // ---- epilogue ----
#pragma unroll
    for (int i = 0; i < 4; i++) {
        int r0 = wm * 64 + i * 16 + (lane >> 2);
#pragma unroll
        for (int j = 0; j < 4; j++) {
            int c0 = n0 + wn * 32 + j * 8 + (lane & 3) * 2;
            float* cp = C + (crow0 + r0) * (size_t)N + c0;
            float* cp2 = C + (crow0 + r0 + 8) * (size_t)N + c0;
            if (RES) {
                const float* rp = res + (crow0 + r0) * (size_t)N + c0;
                const float* rp2 = res + (crow0 + r0 + 8) * (size_t)N + c0;
                cp[0] = acc[i][j][0] + rp[0];
                cp[1] = acc[i][j][1] + rp[1];
                cp2[0] = acc[i][j][2] + rp2[0];
                cp2[1] = acc[i][j][3] + rp2[1];
            } else {
                cp[0] = acc[i][j][0];
                cp[1] = acc[i][j][1];
                cp2[0] = acc[i][j][2];
                cp2[1] = acc[i][j][3];
            }
        }
    }
}

// ---------------- rmsnorm (emits bf16 hi/lo, optionally fp32) ----------------
template <bool OUT32>
__global__ void rmsnorm_kernel(const float* __restrict__ in, const float* __restrict__ w,
                               float* __restrict__ out32,
                               __nv_bfloat16* __restrict__ oh, __nv_bfloat16* __restrict__ ol) {
    int row = blockIdx.x;
    const float* x = in + (size_t)row * HDIM;
    __shared__ float red[256];
    float s = 0.f;
    for (int i = threadIdx.x; i < HDIM; i += 256) { float v = x[i]; s += v * v; }
    red[threadIdx.x] = s; __syncthreads();
    for (int st = 128; st > 0; st >>= 1) {
        if (threadIdx.x < st) red[threadIdx.x] += red[threadIdx.x + st];
        __syncthreads();
    }
    float inv = rsqrtf(red[0] / (float)HDIM + EPSF);
    for (int i = threadIdx.x; i < HDIM; i += 256) {
        float v = w[i] * x[i] * inv;
        if (OUT32) out32[(size_t)row * HDIM + i] = v;
        __nv_bfloat16 h, l;
        splitw(v, h, l);
        oh[(size_t)row * HDIM + i] = h;
        ol[(size_t)row * HDIM + i] = l;
    }
}

// ---------------- fp32 SGEMM (attention + logits) ----------------
template <bool RES, int KM>
__global__ void sgemm_kernel(const float* __restrict__ A, const float* __restrict__ B,
                             float* __restrict__ C, const float* __restrict__ res,
                             int M, int N, int K, int lda, int ldb, int ldc,
                             long sA, long sB, long sC, int bdiv) {
    int z = blockIdx.z;
    int row0 = blockIdx.y * 128, col0 = blockIdx.x * 128;
    if (KM == 1 && col0 > row0) return;
    int Keff = K;
    if (KM == 2) Keff = (row0 + 128 < K) ? row0 + 128 : K;
    A += (size_t)z * sA;
    B += (size_t)(z / bdiv) * sB;
    C += (size_t)z * sC;
    if (RES) res += (size_t)z * sC;
    __shared__ float As[8][128];
    __shared__ float Bs[8][128];
    int tid = threadIdx.x;
    int tx = tid & 15, ty = tid >> 4;
    int arow = tid >> 1;
    int acol = (tid & 1) * 4;
    int brow = tid >> 5;
    int bcol = (tid & 31) * 4;
    const float* Aptr = A + (size_t)(row0 + arow) * lda + acol;
    const float* Bptr = B + (size_t)brow * ldb + col0 + bcol;
    bool bok = (col0 + bcol) < N;
    float acc[8][8];
#pragma unroll
    for (int i = 0; i < 8; i++)
#pragma unroll
        for (int j = 0; j < 8; j++) acc[i][j] = 0.f;

    for (int k0 = 0; k0 < Keff; k0 += 8) {
        float4 av = *(const float4*)(Aptr + k0);
        As[acol + 0][arow] = av.x;
        As[acol + 1][arow] = av.y;
        As[acol + 2][arow] = av.z;
        As[acol + 3][arow] = av.w;
        float4 bv = make_float4(0.f, 0.f, 0.f, 0.f);
        if (bok) bv = *(const float4*)(Bptr + (size_t)k0 * ldb);
        *(float4*)&Bs[brow][bcol] = bv;
        __syncthreads();
#pragma unroll
        for (int kk = 0; kk < 8; kk++) {
            float am[8], bn[8];
#pragma unroll
            for (int i = 0; i < 8; i++) am[i] = As[kk][ty * 8 + i];
#pragma unroll
            for (int j = 0; j < 8; j++) bn[j] = Bs[kk][tx * 8 + j];
#pragma unroll
            for (int i = 0; i < 8; i++)
#pragma unroll
                for (int j = 0; j < 8; j++) acc[i][j] += am[i] * bn[j];
        }
        __syncthreads();
    }
#pragma unroll
    for (int i = 0; i < 8; i++) {
        int r = row0 + ty * 8 + i;
#pragma unroll
        for (int j = 0; j < 8; j++) {
            int c = col0 + tx * 8 + j;
            if (c < N) {
                float v = acc[i][j];
                if (RES) v += res[(size_t)r * ldc + c];
                C[(size_t)r * ldc + c] = v;
            }
        }
    }
}

// ---------------- RoPE + qk rmsnorm + layout split ----------------
__global__ void rope_qk_kernel(const float* __restrict__ cosb, const float* __restrict__ sinb,
                               const float* __restrict__ qw, const float* __restrict__ kw) {
    int s = blockIdx.x, kv = blockIdx.y;
    int w = threadIdx.x >> 5, lane = threadIdx.x & 31;
    const float* src = g_qkv + (size_t)s * 2048 + kv * 256 + w * 64;
    float x1 = src[lane], x2 = src[lane + 32];
    float o1, o2;
    if (w < 3) {
        float c1 = cosb[s * 64 + lane], s1 = sinb[s * 64 + lane];
        float c2 = cosb[s * 64 + lane + 32], s2 = sinb[s * 64 + lane + 32];
        o1 = x1 * c1 - x2 * s1;
        o2 = x2 * c2 + x1 * s2;
        float ss = o1 * o1 + o2 * o2;
#pragma unroll
        for (int off = 16; off; off >>= 1) ss += __shfl_xor_sync(0xffffffffu, ss, off);
        float inv = rsqrtf(ss / 64.f + EPSF);
        const float* wt = (w < 2) ? qw : kw;
        o1 *= inv * wt[lane];
        o2 *= inv * wt[lane + 32];
    } else {
        o1 = x1; o2 = x2;
    }
    if (w < 2) {
        int head = kv * 2 + w;
        g_q[(size_t)head * 65536 + s * 64 + lane] = o1;
        g_q[(size_t)head * 65536 + s * 64 + lane + 32] = o2;
    } else if (w == 2) {
        g_kT[(size_t)kv * 65536 + lane * 1024 + s] = o1;
        g_kT[(size_t)kv * 65536 + (lane + 32) * 1024 + s] = o2;
    } else {
        g_v[(size_t)kv * 65536 + s * 64 + lane] = o1;
        g_v[(size_t)kv * 65536 + s * 64 + lane + 32] = o2;
    }
}

// ---------------- causal scaled softmax ----------------
__global__ void softmax_kernel() {
    int s = blockIdx.x, h = blockIdx.y;
    float* row = g_scores + ((size_t)h * SEQ + s) * SEQ;
    int n = s + 1;
    __shared__ float red[256];
    int tid = threadIdx.x;
    float m = -INFINITY;
    for (int i = tid; i < n; i += 256) m = fmaxf(m, row[i] * 0.125f);
    red[tid] = m; __syncthreads();
    for (int st = 128; st > 0; st >>= 1) {
        if (tid < st) red[tid] = fmaxf(red[tid], red[tid + st]);
        __syncthreads();
    }
    m = red[0]; __syncthreads();
    float sum = 0.f;
    for (int i = tid; i < n; i += 256) {
        float p = __expf(row[i] * 0.125f - m);
        row[i] = p;
        sum += p;
    }
    red[tid] = sum; __syncthreads();
    for (int st = 128; st > 0; st >>= 1) {
        if (tid < st) red[tid] += red[tid + st];
        __syncthreads();
    }
    float inv = 1.f / red[0];
    for (int i = tid; i < n; i += 256) row[i] *= inv;
    for (int i = n + tid; i < SEQ; i += 256) row[i] = 0.f;
}

// ---------------- shared swiglu -> bf16 hi/lo ----------------
__global__ void swiglu_shared_kernel() {
    int t = blockIdx.x;
    for (int i = threadIdx.x; i < IDIM; i += 256) {
        float a = g_gu[(size_t)t * 6144 + i];
        float b = g_gu[(size_t)t * 6144 + 3072 + i];
        float v = a * (b / (1.f + __expf(-b)));
        __nv_bfloat16 h, l;
        splitw(v, h, l);
        g_hs_h[(size_t)t * 3072 + i] = h;
        g_hs_l[(size_t)t * 3072 + i] = l;
    }
}

// ---------------- gate softmax + top-8 ----------------
__global__ void topk_kernel() {
    int t = blockIdx.x;
    int tid = threadIdx.x;
    __shared__ float gate[NEXP];
    __shared__ float red[NEXP];
    float lg = g_logits[t * NEXP + tid];
    red[tid] = lg; __syncthreads();
    for (int st = 32; st > 0; st >>= 1) {
        if (tid < st) red[tid] = fmaxf(red[tid], red[tid + st]);
        __syncthreads();
    }
    float m = red[0]; __syncthreads();
    float e = __expf(lg - m);
    gate[tid] = e;
    red[tid] = e; __syncthreads();
    for (int st = 32; st > 0; st >>= 1) {
        if (tid < st) red[tid] += red[tid + st];
        __syncthreads();
    }
    float inv = 1.f / red[0];
    __syncthreads();
    gate[tid] = e * inv;
    __syncthreads();
    if (tid == 0) {
        float vals[TOPK];
        int idxs[TOPK];
        float den = 0.f;
        for (int k = 0; k < TOPK; k++) {
            float bv = -INFINITY; int bi = 0;
            for (int i = 0; i < NEXP; i++) {
                float v = gate[i];
                if (v > bv) { bv = v; bi = i; }
            }
            vals[k] = bv; idxs[k] = bi; den += bv;
            gate[bi] = -INFINITY;
        }
        den = fmaxf(den, 1.19209290e-07f);
        for (int k = 0; k < TOPK; k++) {
            g_assign_e[t * TOPK + k] = idxs[k];
            g_assign_w[t * TOPK + k] = vals[k] / den;
        }
    }
}

// ---------------- routing ----------------
__global__ void route_kernel() {
    int e = threadIdx.x;
    int cnt = 0;
    for (int i = 0; i < SEQ * TOPK; i++) {
        if (g_assign_e[i] == e) {
            g_assign_p[i] = cnt;
            if (cnt < CAP) g_slot_token[e * CAP + cnt] = i >> 3;
            cnt++;
        }
    }
    g_count[e] = cnt < CAP ? cnt : CAP;
}

// ---------------- expert swiglu -> bf16 hi/lo ----------------
__global__ void swiglu_expert_kernel() {
    int t = blockIdx.x;
    int e = t >> 2;
    int slot0 = (t & 3) * 128 + blockIdx.y * 16;
    int cnt = g_count[e];
    if (slot0 >= cnt) return;
    int send = slot0 + 16;
    if (send > cnt) send = cnt;
    for (int slot = slot0; slot < send; slot++) {
        size_t r = (size_t)e * CAP + slot;
        for (int i = threadIdx.x; i < IDIM; i += 256) {
            float a = g_gue[r * 6144 + i];
            float b = g_gue[r * 6144 + 3072 + i];
            float v = a * (b / (1.f + __expf(-b)));
            __nv_bfloat16 h, l;
            splitw(v, h, l);
            g_hexp_h[r * 3072 + i] = h;
            g_hexp_l[r * 3072 + i] = l;
        }
    }
}

// ---------------- final combine ----------------
__global__ void combine_kernel(float* __restrict__ out) {
    int t = blockIdx.x;
    int tid = threadIdx.x;
    __shared__ float w[TOPK];
    __shared__ int rr[TOPK];
    if (tid < TOPK) {
        int i = t * TOPK + tid;
        int p = g_assign_p[i];
        int e = g_assign_e[i];
        bool valid = p < CAP;
        w[tid] = valid ? g_assign_w[i] : 0.f;
        rr[tid] = e * CAP + (valid ? p : 0);
    }
    __syncthreads();
    for (int h = tid; h < HDIM; h += 256) {
        float v = g_h1[(size_t)t * HDIM + h] + g_sharedo[(size_t)t * HDIM + h];
#pragma unroll
        for (int k = 0; k < TOPK; k++) v += w[k] * g_ye[(size_t)rr[k] * HDIM + h];
        out[(size_t)t * HDIM + h] = v;
    }
}

// ---------------- launch ----------------
extern "C" void kernel_launch(void* const* d_in, const int* in_sizes, int n_in,
                              void* d_out, int out_size) {
    const float* hidden = (const float*)d_in[0];
    const float* cosb = (const float*)d_in[1];
    const float* sinb = (const float*)d_in[2];
    const float* ln1_w = (const float*)d_in[3];
    const float* ln2_w = (const float*)d_in[4];
    const float* Wqkv = (const float*)d_in[5];
    const float* Wo = (const float*)d_in[6];
    const float* qnorm_w = (const float*)d_in[7];
    const float* knorm_w = (const float*)d_in[8];
    const float* Wgu_sh = (const float*)d_in[9];
    const float* Wd_sh = (const float*)d_in[10];
    const float* Wgate = (const float*)d_in[11];
    const float* Wgu_ex = (const float*)d_in[12];
    const float* Wd_ex = (const float*)d_in[13];
    float* out = (float*)d_out;

    float *pqkv, *pq, *pkT, *pv, *pscores, *pattn, *ph1, *px2, *pgu, *psh, *plog, *pgue, *pye;
    __nv_bfloat16 *pxh, *pxl, *px2h, *px2l, *phsh, *phsl, *pheh, *phel;
    cudaGetSymbolAddress((void**)&pxh, g_x_h);
    cudaGetSymbolAddress((void**)&pxl, g_x_l);
    cudaGetSymbolAddress((void**)&pqkv, g_qkv);
    cudaGetSymbolAddress((void**)&pq, g_q);
    cudaGetSymbolAddress((void**)&pkT, g_kT);
    cudaGetSymbolAddress((void**)&pv, g_v);
    cudaGetSymbolAddress((void**)&pscores, g_scores);
    cudaGetSymbolAddress((void**)&pattn, g_attn);
    cudaGetSymbolAddress((void**)&ph1, g_h1);
    cudaGetSymbolAddress((void**)&px2, g_x2);
    cudaGetSymbolAddress((void**)&px2h, g_x2_h);
    cudaGetSymbolAddress((void**)&px2l, g_x2_l);
    cudaGetSymbolAddress((void**)&pgu, g_gu);
    cudaGetSymbolAddress((void**)&phsh, g_hs_h);
    cudaGetSymbolAddress((void**)&phsl, g_hs_l);
    cudaGetSymbolAddress((void**)&psh, g_sharedo);
    cudaGetSymbolAddress((void**)&plog, g_logits);
    cudaGetSymbolAddress((void**)&pgue, g_gue);
    cudaGetSymbolAddress((void**)&pheh, g_hexp_h);
    cudaGetSymbolAddress((void**)&phel, g_hexp_l);
    cudaGetSymbolAddress((void**)&pye, g_ye);

    static int attr_done = 0;
    if (!attr_done) {
        cudaFuncSetAttribute(bf_gemm<0, false, true>, cudaFuncAttributeMaxDynamicSharedMemorySize, SMEM_BYTES);
        cudaFuncSetAttribute(bf_gemm<0, true, false>, cudaFuncAttributeMaxDynamicSharedMemorySize, SMEM_BYTES);
        cudaFuncSetAttribute(bf_gemm<1, false, true>, cudaFuncAttributeMaxDynamicSharedMemorySize, SMEM_BYTES);
        cudaFuncSetAttribute(bf_gemm<2, false, true>, cudaFuncAttributeMaxDynamicSharedMemorySize, SMEM_BYTES);
        attr_done = 1;
    }

    // 1. x = rmsnorm(hidden, ln1) -> bf16 hi/lo
    rmsnorm_kernel<false><<<SEQ, 256>>>(hidden, ln1_w, nullptr, pxh, pxl);
    // 2. qkv = x @ Wqkv
    bf_gemm<0, false, true><<<dim3(16, 8), 256, SMEM_BYTES>>>(pxh, pxl, Wqkv, pqkv, nullptr, 2048, 1024);
    // 3. rope + qknorm + split
    rope_qk_kernel<<<dim3(SEQ, KVHEADS), 128>>>(cosb, sinb, qnorm_w, knorm_w);
    // 4. scores = q @ k^T (causal block-skip)
    sgemm_kernel<false, 1><<<dim3(8, 8, NHEADS), 256>>>(pq, pkT, pscores, nullptr,
        1024, 1024, 64, 64, 1024, 1024, 65536, 65536, 1048576, 2);
    // 5. causal softmax
    softmax_kernel<<<dim3(SEQ, NHEADS), 256>>>();
    // 6. attn = P @ V (K capped per row-block)
    sgemm_kernel<false, 2><<<dim3(1, 8, NHEADS), 256>>>(pscores, pv, pattn, nullptr,
        1024, 64, 1024, 1024, 64, 1024, 1048576, 65536, 64, 2);
    // 7. h1 = attn @ Wo + hidden (A fp32, in-loop split)
    bf_gemm<0, true, false><<<dim3(8, 8), 256, SMEM_BYTES>>>(pattn, nullptr, Wo, ph1, hidden, 1024, 1024);
    // 8. x2 = rmsnorm(h1, ln2) -> fp32 + bf16 hi/lo
    rmsnorm_kernel<true><<<SEQ, 256>>>(ph1, ln2_w, px2, px2h, px2l);
    // 9. gu = x2 @ Wgu_shared
    bf_gemm<0, false, true><<<dim3(48, 8), 256, SMEM_BYTES>>>(px2h, px2l, Wgu_sh, pgu, nullptr, 6144, 1024);
    // 10. swiglu -> hs hi/lo
    swiglu_shared_kernel<<<SEQ, 256>>>();
    // 11. shared = hs @ Wd_shared
    bf_gemm<0, false, true><<<dim3(8, 8), 256, SMEM_BYTES>>>(phsh, phsl, Wd_sh, psh, nullptr, 1024, 3072);
    // 12. logits = x2 @ Wgate
    sgemm_kernel<false, 0><<<dim3(1, 8, 1), 256>>>(px2, Wgate, plog, nullptr,
        1024, 64, 1024, 1024, 64, 64, 0, 0, 0, 1);
    // 13. softmax + top8
    topk_kernel<<<SEQ, 64>>>();
    // 14. routing
    route_kernel<<<1, 64>>>();
    // 15. expert GEMM1 (gathered) -> gu_e
    bf_gemm<1, false, true><<<dim3(48, 256), 256, SMEM_BYTES>>>(px2h, px2l, Wgu_ex, pgue, nullptr, 6144, 1024);
    // 16. expert swiglu -> hexp hi/lo
    swiglu_expert_kernel<<<dim3(256, 8), 256>>>();
    // 17. expert GEMM2 -> ye
    bf_gemm<2, false, true><<<dim3(8, 256), 256, SMEM_BYTES>>>(pheh, phel, Wd_ex, pye, nullptr, 1024, 3072);
    // 18. out = h1 + shared + moe
    combine_kernel<<<SEQ, 256>>>(out);
}

// round 6
// speedup vs baseline: 2.7155x; 1.1734x over previous
#include <cuda_runtime.h>
#include <cuda_fp16.h>
#include <math.h>
#include <stdint.h>

#define SEQ 1024
#define HDIM 1024
#define NHEADS 16
#define KVHEADS 8
#define HSZ 64
#define NEXP 64
#define TOPK 8
#define CAP 512
#define IDIM 3072
#define EPSF 1e-6f

// ---------------- scratch ----------------
__device__ __half g_x_h[SEQ * HDIM];
__device__ __half g_x_l[SEQ * HDIM];
__device__ float g_qkv[SEQ * 2048];
__device__ float g_q[NHEADS * SEQ * HSZ];
__device__ float g_kT[KVHEADS * HSZ * SEQ];
__device__ float g_v[KVHEADS * SEQ * HSZ];
__device__ float g_scores[(size_t)NHEADS * SEQ * SEQ];
__device__ float g_attn[SEQ * HDIM];
__device__ float g_h1[SEQ * HDIM];
__device__ float g_x2[SEQ * HDIM];
__device__ __half g_x2_h[SEQ * HDIM];
__device__ __half g_x2_l[SEQ * HDIM];
__device__ __half g_hs_h[SEQ * IDIM];
__device__ __half g_hs_l[SEQ * IDIM];
__device__ float g_sharedo[SEQ * HDIM];
__device__ float g_logits[SEQ * NEXP];
__device__ int   g_assign_e[SEQ * TOPK];
__device__ float g_assign_w[SEQ * TOPK];
__device__ int   g_assign_p[SEQ * TOPK];
__device__ int   g_slot_token[NEXP * CAP];
__device__ int   g_count[NEXP];
__device__ __half g_hexp_h[(size_t)NEXP * CAP * IDIM];
__device__ __half g_hexp_l[(size_t)NEXP * CAP * IDIM];
__device__ float g_ye[(size_t)NEXP * CAP * HDIM];

// ---------------- helpers ----------------
__device__ __forceinline__ uint32_t smem_u32(const void* p) {
    uint32_t a;
    asm("{ .reg .u64 t; cvta.to.shared.u64 t, %1; cvt.u32.u64 %0, t; }" : "=r"(a) : "l"(p));
    return a;
}
__device__ __forceinline__ uint32_t pack_h2(float a, float b) {
    __half2 t = __floats2half2_rn(a, b);
    return *reinterpret_cast<uint32_t*>(&t);
}
__device__ __forceinline__ void splitw_h(float v, __half& h, __half& l) {
    __half hh = __float2half_rn(v);
    h = hh;
    l = __float2half_rn(v - __half2float(hh));
}
// fp32x4 -> fp16 hi uint2 + lo uint2
__device__ __forceinline__ void split4h(float4 v, uint2& h, uint2& l) {
    __half2 h0 = __floats2half2_rn(v.x, v.y);
    __half2 h1 = __floats2half2_rn(v.z, v.w);
    float2 f0 = __half22float2(h0);
    float2 f1 = __half22float2(h1);
    __half2 l0 = __floats2half2_rn(v.x - f0.x, v.y - f0.y);
    __half2 l1 = __floats2half2_rn(v.z - f1.x, v.w - f1.y);
    h.x = *reinterpret_cast<uint32_t*>(&h0);
    h.y = *reinterpret_cast<uint32_t*>(&h1);
    l.x = *reinterpret_cast<uint32_t*>(&l0);
    l.y = *reinterpret_cast<uint32_t*>(&l1);
}
__device__ __forceinline__ void ldmx4(uint32_t* r, uint32_t addr) {
    asm volatile("ldmatrix.sync.aligned.m8n8.x4.shared.b16 {%0,%1,%2,%3}, [%4];"
                 : "=r"(r[0]), "=r"(r[1]), "=r"(r[2]), "=r"(r[3]) : "r"(addr));
}
__device__ __forceinline__ void ldmx2t(uint32_t* r, uint32_t addr) {
    asm volatile("ldmatrix.sync.aligned.m8n8.x2.trans.shared.b16 {%0,%1}, [%2];"
                 : "=r"(r[0]), "=r"(r[1]) : "r"(addr));
}
__device__ __forceinline__ void mma_h(float* d, const uint32_t* a, const uint32_t* b) {
    asm volatile("mma.sync.aligned.m16n8k16.row.col.f32.f16.f16.f32 "
                 "{%0,%1,%2,%3}, {%4,%5,%6,%7}, {%8,%9}, {%0,%1,%2,%3};"
                 : "+f"(d[0]), "+f"(d[1]), "+f"(d[2]), "+f"(d[3])
                 : "r"(a[0]), "r"(a[1]), "r"(a[2]), "r"(a[3]), "r"(b[0]), "r"(b[1]));
}

// ---------------- fp16 split-precision HMMA GEMM, double-buffered ----------------
#define APAD 40
#define BPAD 136
#define A_EL (128 * APAD)
#define B_EL (32 * BPAD)
// halves offsets: [Ah buf0][Ah buf1][Al buf0][Al buf1][B buf0][B buf1][Bl buf0][Bl buf1]
#define OFF_AH(b) ((b) * A_EL)
#define OFF_AL(b) (2 * A_EL + (b) * A_EL)
#define OFF_B(b)  (4 * A_EL + (b) * B_EL)
#define OFF_BL(b) (4 * A_EL + 2 * B_EL + (b) * B_EL)
#define SM2_BYTES ((4 * A_EL + 2 * B_EL) * 2)
#define SM3_BYTES ((4 * A_EL + 4 * B_EL) * 2)

// MODE 0 dense / 1 expert+gather / 2 expert direct. ASPLIT: A pre-split fp16.
// NPASS 2: passes ah*b + al*b (weights single fp16). NPASS 3: + ah*bl (weights hi/lo).
// FUSE: B columns interleaved (a_j,b_j) from the two halves of [K, N]; epilogue writes
//       a*silu(b) as fp16 hi/lo to Oh/Ol with row width N/2.
template <int MODE, bool RES, bool ASPLIT, int NPASS, bool FUSE>
__global__ void __launch_bounds__(256, 1) hf_gemm(const void* __restrict__ Av,
                                                  const __half* __restrict__ Alp,
                                                  const float* __restrict__ B,
                                                  float* __restrict__ C,
                                                  const float* __restrict__ res,
                                                  __half* __restrict__ Oh,
                                                  __half* __restrict__ Ol,
                                                  int N, int K) {
    extern __shared__ __align__(16) __half sm[];
    int tid = threadIdx.x, lane = tid & 31, wid = tid >> 5;
    int wm = wid & 1, wn = wid >> 1;

    int e = 0, slot0 = 0, cnt = 128;
    size_t crow0;
    if (MODE == 0) {
        crow0 = (size_t)blockIdx.y * 128;
    } else {
        int t = blockIdx.y;
        e = t >> 2;
        slot0 = (t & 3) * 128;
        int c = g_count[e] - slot0;
        if (c <= 0) return;
        cnt = c < 128 ? c : 128;
        B += (size_t)e * K * N;
        crow0 = (size_t)e * CAP + slot0;
    }
    int n0 = blockIdx.x * 128;

    int a_row = tid >> 1;
    int a_q = (tid & 1) * 16;      // 16 elements per thread
    int b_row = tid >> 3;          // 32 k-rows, 8 threads each
    int b_q = (tid & 7) * 16;      // 16 cols per thread

    bool aok = a_row < cnt;
    size_t a_off;
    if (MODE == 1) {
        int tok = aok ? g_slot_token[e * CAP + slot0 + a_row] : 0;
        a_off = (size_t)tok * K + a_q;
    } else {
        a_off = (crow0 + a_row) * (size_t)K + a_q;
    }
    const float* aptr_f = (const float*)Av + a_off;
    const __half* aptr_h = (const __half*)Av + a_off;
    const __half* aptr_l = Alp + a_off;
    // B pointers
    const float* bptr = B + (size_t)b_row * N + n0 + b_q;          // generic
    const float* bptr_a = B + (size_t)b_row * N + ((n0 + b_q) >> 1); // FUSE a-half
    const float* bptr_b = bptr_a + (N >> 1);                         // FUSE b-half

    float acc[4][4][4];
#pragma unroll
    for (int i = 0; i < 4; i++)
#pragma unroll
        for (int j = 0; j < 4; j++)
#pragma unroll
            for (int v = 0; v < 4; v++) acc[i][j][v] = 0.f;

    uint32_t sbase = smem_u32(sm);
    const uint4 z4 = make_uint4(0, 0, 0, 0);

    uint4 pah[2], pal[2];
    float4 pa[4];
    float4 pb[4];

    // ---- prologue: load chunk 0 into registers ----
    if (ASPLIT) {
        pah[0] = aok ? *(const uint4*)(aptr_h) : z4;
        pah[1] = aok ? *(const uint4*)(aptr_h + 8) : z4;
        pal[0] = aok ? *(const uint4*)(aptr_l) : z4;
        pal[1] = aok ? *(const uint4*)(aptr_l + 8) : z4;
    } else {
#pragma unroll
        for (int j = 0; j < 4; j++)
            pa[j] = aok ? *(const float4*)(aptr_f + j * 4) : make_float4(0.f, 0.f, 0.f, 0.f);
    }
    if (FUSE) {
        pb[0] = *(const float4*)(bptr_a);
        pb[1] = *(const float4*)(bptr_a + 4);
        pb[2] = *(const float4*)(bptr_b);
        pb[3] = *(const float4*)(bptr_b + 4);
    } else {
#pragma unroll
        for (int j = 0; j < 4; j++) pb[j] = *(const float4*)(bptr + j * 4);
    }

    // ---- store helper (emitted twice: prologue + loop) ----
    auto store_stage = [&](int buf) {
        __half* AH = sm + OFF_AH(buf);
        __half* AL = sm + OFF_AL(buf);
        __half* BP = sm + OFF_B(buf);
        int oa = a_row * APAD + a_q;
        if (ASPLIT) {
            *(uint4*)(AH + oa) = pah[0];
            *(uint4*)(AH + oa + 8) = pah[1];
            *(uint4*)(AL + oa) = pal[0];
            *(uint4*)(AL + oa + 8) = pal[1];
        } else {
#pragma unroll
            for (int j = 0; j < 4; j++) {
                uint2 h, l;
                split4h(pa[j], h, l);
                *(uint2*)(AH + oa + j * 4) = h;
                *(uint2*)(AL + oa + j * 4) = l;
            }
        }
        int ob = b_row * BPAD + b_q;
        if (FUSE) {
            // interleave (a_i, b_i) pairs
            const float* fa = (const float*)&pb[0];
            const float* fb = (const float*)&pb[2];
            uint32_t q[8];
#pragma unroll
            for (int i = 0; i < 8; i++) q[i] = pack_h2(fa[i], fb[i]);
            *(uint4*)(BP + ob) = make_uint4(q[0], q[1], q[2], q[3]);
            *(uint4*)(BP + ob + 8) = make_uint4(q[4], q[5], q[6], q[7]);
        } else if (NPASS == 2) {
            const float* f = (const float*)&pb[0];
            uint32_t q[8];
#pragma unroll
            for (int i = 0; i < 8; i++) q[i] = pack_h2(f[2 * i], f[2 * i + 1]);
            *(uint4*)(BP + ob) = make_uint4(q[0], q[1], q[2], q[3]);
            *(uint4*)(BP + ob + 8) = make_uint4(q[4], q[5], q[6], q[7]);
        } else {
            __half* BL = sm + OFF_BL(buf);
#pragma unroll
            for (int j = 0; j < 4; j++) {
                uint2 h, l;
                split4h(pb[j], h, l);
                *(uint2*)(BP + ob + j * 4) = h;
                *(uint2*)(BL + ob + j * 4) = l;
            }
        }
    };

    store_stage(0);
    __syncthreads();

    int nk = K >> 5;
    for (int c = 0; c < nk; c++) {
        int cur = c & 1;
        bool more = (c + 1) < nk;
        if (more) {
            int k1 = (c + 1) << 5;
            if (ASPLIT) {
                pah[0] = aok ? *(const uint4*)(aptr_h + k1) : z4;
                pah[1] = aok ? *(const uint4*)(aptr_h + k1 + 8) : z4;
                pal[0] = aok ? *(const uint4*)(aptr_l + k1) : z4;
                pal[1] = aok ? *(const uint4*)(aptr_l + k1 + 8) : z4;
            } else {
#pragma unroll
                for (int j = 0; j < 4; j++)
                    pa[j] = aok ? *(const float4*)(aptr_f + k1 + j * 4) : make_float4(0.f, 0.f, 0.f, 0.f);
            }
            size_t krow = (size_t)k1 * N;
            if (FUSE) {
                pb[0] = *(const float4*)(bptr_a + krow);
                pb[1] = *(const float4*)(bptr_a + krow + 4);
                pb[2] = *(const float4*)(bptr_b + krow);
                pb[3] = *(const float4*)(bptr_b + krow + 4);
            } else {
#pragma unroll
                for (int j = 0; j < 4; j++) pb[j] = *(const float4*)(bptr + krow + j * 4);
            }
        }

        uint32_t aho = sbase + OFF_AH(cur) * 2;
        uint32_t alo = sbase + OFF_AL(cur) * 2;
        uint32_t bo = sbase + OFF_B(cur) * 2;
        uint32_t blo = sbase + OFF_BL(cur) * 2;
#pragma unroll
        for (int ks = 0; ks < 2; ks++) {
            uint32_t ah[4][4], al[4][4], bh[4][2], bl[4][2];
#pragma unroll
            for (int i = 0; i < 4; i++) {
                uint32_t off = ((wm * 64 + i * 16 + (lane & 15)) * APAD + ks * 16 + (lane >> 4) * 8) * 2;
                ldmx4(ah[i], aho + off);
                ldmx4(al[i], alo + off);
            }
#pragma unroll
            for (int j = 0; j < 4; j++) {
                uint32_t off = ((ks * 16 + (lane & 15)) * BPAD + wn * 32 + j * 8) * 2;
                ldmx2t(bh[j], bo + off);
                if (NPASS == 3) ldmx2t(bl[j], blo + off);
            }
#pragma unroll
            for (int i = 0; i < 4; i++)
#pragma unroll
                for (int j = 0; j < 4; j++) mma_h(acc[i][j], ah[i], bh[j]);
#pragma unroll
            for (int i = 0; i < 4; i++)
#pragma unroll
                for (int j = 0; j < 4; j++) mma_h(acc[i][j], al[i], bh[j]);
            if (NPASS == 3) {
#pragma unroll
                for (int i = 0; i < 4; i++)
#pragma unroll
                    for (int j = 0; j < 4; j++) mma_h(acc[i][j], ah[i], bl[j]);
            }
        }

        if (more) store_stage(cur ^ 1);
        __syncthreads();
    }

    // ---- epilogue ----
    if (FUSE) {
        int NP = N >> 1;
#pragma unroll
        for (int i = 0; i < 4; i++) {
            int r0 = wm * 64 + i * 16 + (lane >> 2);
#pragma unroll
            for (int j = 0; j < 4; j++) {
                int c0 = n0 + wn * 32 + j * 8 + (lane & 3) * 2;
                int p = c0 >> 1;
                {
                    float a = acc[i][j][0], b = acc[i][j][1];
                    float h = a * (b / (1.f + __expf(-b)));
                    __half hh, hl;
                    splitw_h(h, hh, hl);
                    size_t o = (crow0 + r0) * (size_t)NP + p;
                    Oh[o] = hh; Ol[o] = hl;
                }
                {
                    float a = acc[i][j][2], b = acc[i][j][3];
                    float h = a * (b / (1.f + __expf(-b)));
                    __half hh, hl;
                    splitw_h(h, hh, hl);
                    size_t o = (crow0 + r0 + 8) * (size_t)NP + p;
                    Oh[o] = hh; Ol[o] = hl;
                }
            }
        }
    } else {
#pragma unroll
        for (int i = 0; i < 4; i++) {
            int r0 = wm * 64 + i * 16 + (lane >> 2);
#pragma unroll
            for (int j = 0; j < 4; j++) {
                int c0 = n0 + wn * 32 + j * 8 + (lane & 3) * 2;
                float* cp = C + (crow0 + r0) * (size_t)N + c0;
                float* cp2 = C + (crow0 + r0 + 8) * (size_t)N + c0;
                if (RES) {
                    const float* rp = res + (crow0 + r0) * (size_t)N + c0;
                    const float* rp2 = res + (crow0 + r0 + 8) * (size_t)N + c0;
                    cp[0] = acc[i][j][0] + rp[0];
                    cp[1] = acc[i][j][1] + rp[1];
                    cp2[0] = acc[i][j][2] + rp2[0];
                    cp2[1] = acc[i][j][3] + rp2[1];
                } else {
                    cp[0] = acc[i][j][0];
                    cp[1] = acc[i][j][1];
                    cp2[0] = acc[i][j][2];
                    cp2[1] = acc[i][j][3];
                }
            }
        }
    }
}

// ---------------- rmsnorm (emits fp16 hi/lo, optionally fp32) ----------------
template <bool OUT32>
__global__ void rmsnorm_kernel(const float* __restrict__ in, const float* __restrict__ w,
                               float* __restrict__ out32,
                               __half* __restrict__ oh, __half* __restrict__ ol) {
    int row = blockIdx.x;
    const float* x = in + (size_t)row * HDIM;
    __shared__ float red[256];
    float s = 0.f;
    for (int i = threadIdx.x; i < HDIM; i += 256) { float v = x[i]; s += v * v; }
    red[threadIdx.x] = s; __syncthreads();
    for (int st = 128; st > 0; st >>= 1) {
        if (threadIdx.x < st) red[threadIdx.x] += red[threadIdx.x + st];
        __syncthreads();
    }
    float inv = rsqrtf(red[0] / (float)HDIM + EPSF);
    for (int i = threadIdx.x; i < HDIM; i += 256) {
        float v = w[i] * x[i] * inv;
        if (OUT32) out32[(size_t)row * HDIM + i] = v;
        __half h, l;
        splitw_h(v, h, l);
        oh[(size_t)row * HDIM + i] = h;
        ol[(size_t)row * HDIM + i] = l;
    }
}

// ---------------- fp32 SGEMM (attention + logits) ----------------
template <bool RES, int KM>
__global__ void sgemm_kernel(const float* __restrict__ A, const float* __restrict__ B,
                             float* __restrict__ C, const float* __restrict__ res,
                             int M, int N, int K, int lda, int ldb, int ldc,
                             long sA, long sB, long sC, int bdiv) {
    int z = blockIdx.z;
    int row0 = blockIdx.y * 128, col0 = blockIdx.x * 128;
    if (KM == 1 && col0 > row0) return;
    int Keff = K;
    if (KM == 2) Keff = (row0 + 128 < K) ? row0 + 128 : K;
    A += (size_t)z * sA;
    B += (size_t)(z / bdiv) * sB;
    C += (size_t)z * sC;
    if (RES) res += (size_t)z * sC;
    __shared__ float As[8][128];
    __shared__ float Bs[8][128];
    int tid = threadIdx.x;
    int tx = tid & 15, ty = tid >> 4;
    int arow = tid >> 1;
    int acol = (tid & 1) * 4;
    int brow = tid >> 5;
    int bcol = (tid & 31) * 4;
    const float* Aptr = A + (size_t)(row0 + arow) * lda + acol;
    const float* Bptr = B + (size_t)brow * ldb + col0 + bcol;
    bool bok = (col0 + bcol) < N;
    float acc[8][8];
#pragma unroll
    for (int i = 0; i < 8; i++)
#pragma unroll
        for (int j = 0; j < 8; j++) acc[i][j] = 0.f;

    for (int k0 = 0; k0 < Keff; k0 += 8) {
        float4 av = *(const float4*)(Aptr + k0);
        As[acol + 0][arow] = av.x;
        As[acol + 1][arow] = av.y;
        As[acol + 2][arow] = av.z;
        As[acol + 3][arow] = av.w;
        float4 bv = make_float4(0.f, 0.f, 0.f, 0.f);
        if (bok) bv = *(const float4*)(Bptr + (size_t)k0 * ldb);
        *(float4*)&Bs[brow][bcol] = bv;
        __syncthreads();
#pragma unroll
        for (int kk = 0; kk < 8; kk++) {
            float am[8], bn[8];
#pragma unroll
            for (int i = 0; i < 8; i++) am[i] = As[kk][ty * 8 + i];
#pragma unroll
            for (int j = 0; j < 8; j++) bn[j] = Bs[kk][tx * 8 + j];
#pragma unroll
            for (int i = 0; i < 8; i++)
#pragma unroll
                for (int j = 0; j < 8; j++) acc[i][j] += am[i] * bn[j];
        }
        __syncthreads();
    }
#pragma unroll
    for (int i = 0; i < 8; i++) {
        int r = row0 + ty * 8 + i;
#pragma unroll
        for (int j = 0; j < 8; j++) {
            int c = col0 + tx * 8 + j;
            if (c < N) {
                float v = acc[i][j];
                if (RES) v += res[(size_t)r * ldc + c];
                C[(size_t)r * ldc + c] = v;
            }
        }
    }
}

// ---------------- RoPE + qk rmsnorm + layout split ----------------
__global__ void rope_qk_kernel(const float* __restrict__ cosb, const float* __restrict__ sinb,
                               const float* __restrict__ qw, const float* __restrict__ kw) {
    int s = blockIdx.x, kv = blockIdx.y;
    int w = threadIdx.x >> 5, lane = threadIdx.x & 31;
    const float* src = g_qkv + (size_t)s * 2048 + kv * 256 + w * 64;
    float x1 = src[lane], x2 = src[lane + 32];
    float o1, o2;
    if (w < 3) {
        float c1 = cosb[s * 64 + lane], s1 = sinb[s * 64 + lane];
        float c2 = cosb[s * 64 + lane + 32], s2 = sinb[s * 64 + lane + 32];
        o1 = x1 * c1 - x2 * s1;
        o2 = x2 * c2 + x1 * s2;
        float ss = o1 * o1 + o2 * o2;
#pragma unroll
        for (int off = 16; off; off >>= 1) ss += __shfl_xor_sync(0xffffffffu, ss, off);
        float inv = rsqrtf(ss / 64.f + EPSF);
        const float* wt = (w < 2) ? qw : kw;
        o1 *= inv * wt[lane];
        o2 *= inv * wt[lane + 32];
    } else {
        o1 = x1; o2 = x2;
    }
    if (w < 2) {
        int head = kv * 2 + w;
        g_q[(size_t)head * 65536 + s * 64 + lane] = o1;
        g_q[(size_t)head * 65536 + s * 64 + lane + 32] = o2;
    } else if (w == 2) {
        g_kT[(size_t)kv * 65536 + lane * 1024 + s] = o1;
        g_kT[(size_t)kv * 65536 + (lane + 32) * 1024 + s] = o2;
    } else {
        g_v[(size_t)kv * 65536 + s * 64 + lane] = o1;
        g_v[(size_t)kv * 65536 + s * 64 + lane + 32] = o2;
    }
}

// ---------------- causal scaled softmax ----------------
__global__ void softmax_kernel() {
    int s = blockIdx.x, h = blockIdx.y;
    float* row = g_scores + ((size_t)h * SEQ + s) * SEQ;
    int n = s + 1;
    __shared__ float red[256];
    int tid = threadIdx.x;
    float m = -INFINITY;
    for (int i = tid; i < n; i += 256) m = fmaxf(m, row[i] * 0.125f);
    red[tid] = m; __syncthreads();
    for (int st = 128; st > 0; st >>= 1) {
        if (tid < st) red[tid] = fmaxf(red[tid], red[tid + st]);
        __syncthreads();
    }
    m = red[0]; __syncthreads();
    float sum = 0.f;
    for (int i = tid; i < n; i += 256) {
        float p = __expf(row[i] * 0.125f - m);
        row[i] = p;
        sum += p;
    }
    red[tid] = sum; __syncthreads();
    for (int st = 128; st > 0; st >>= 1) {
        if (tid < st) red[tid] += red[tid + st];
        __syncthreads();
    }
    float inv = 1.f / red[0];
    for (int i = tid; i < n; i += 256) row[i] *= inv;
    for (int i = n + tid; i < SEQ; i += 256) row[i] = 0.f;
}

// ---------------- gate softmax + top-8 ----------------
__global__ void topk_kernel() {
    int t = blockIdx.x;
    int tid = threadIdx.x;
    __shared__ float gate[NEXP];
    __shared__ float red[NEXP];
    float lg = g_logits[t * NEXP + tid];
    red[tid] = lg; __syncthreads();
    for (int st = 32; st > 0; st >>= 1) {
        if (tid < st) red[tid] = fmaxf(red[tid], red[tid + st]);
        __syncthreads();
    }
    float m = red[0]; __syncthreads();
    float e = __expf(lg - m);
    gate[tid] = e;
    red[tid] = e; __syncthreads();
    for (int st = 32; st > 0; st >>= 1) {
        if (tid < st) red[tid] += red[tid + st];
        __syncthreads();
    }
    float inv = 1.f / red[0];
    __syncthreads();
    gate[tid] = e * inv;
    __syncthreads();
    if (tid == 0) {
        float vals[TOPK];
        int idxs[TOPK];
        float den = 0.f;
        for (int k = 0; k < TOPK; k++) {
            float bv = -INFINITY; int bi = 0;
            for (int i = 0; i < NEXP; i++) {
                float v = gate[i];
                if (v > bv) { bv = v; bi = i; }
            }
            vals[k] = bv; idxs[k] = bi; den += bv;
            gate[bi] = -INFINITY;
        }
        den = fmaxf(den, 1.19209290e-07f);
        for (int k = 0; k < TOPK; k++) {
            g_assign_e[t * TOPK + k] = idxs[k];
            g_assign_w[t * TOPK + k] = vals[k] / den;
        }
    }
}

// ---------------- routing ----------------
__global__ void route_kernel() {
    int e = threadIdx.x;
    int cnt = 0;
    for (int i = 0; i < SEQ * TOPK; i++) {
        if (g_assign_e[i] == e) {
            g_assign_p[i] = cnt;
            if (cnt < CAP) g_slot_token[e * CAP + cnt] = i >> 3;
            cnt++;
        }
    }
    g_count[e] = cnt < CAP ? cnt : CAP;
}

// ---------------- final combine ----------------
__global__ void combine_kernel(float* __restrict__ out) {
    int t = blockIdx.x;
    int tid = threadIdx.x;
    __shared__ float w[TOPK];
    __shared__ int rr[TOPK];
    if (tid < TOPK) {
        int i = t * TOPK + tid;
        int p = g_assign_p[i];
        int e = g_assign_e[i];
        bool valid = p < CAP;
        w[tid] = valid ? g_assign_w[i] : 0.f;
        rr[tid] = e * CAP + (valid ? p : 0);
    }
    __syncthreads();
    for (int h = tid; h < HDIM; h += 256) {
        float v = g_h1[(size_t)t * HDIM + h] + g_sharedo[(size_t)t * HDIM + h];
#pragma unroll
        for (int k = 0; k < TOPK; k++) v += w[k] * g_ye[(size_t)rr[k] * HDIM + h];
        out[(size_t)t * HDIM + h] = v;
    }
}

// ---------------- launch ----------------
extern "C" void kernel_launch(void* const* d_in, const int* in_sizes, int n_in,
                              void* d_out, int out_size) {
    const float* hidden = (const float*)d_in[0];
    const float* cosb = (const float*)d_in[1];
    const float* sinb = (const float*)d_in[2];
    const float* ln1_w = (const float*)d_in[3];
    const float* ln2_w = (const float*)d_in[4];
    const float* Wqkv = (const float*)d_in[5];
    const float* Wo = (const float*)d_in[6];
    const float* qnorm_w = (const float*)d_in[7];
    const float* knorm_w = (const float*)d_in[8];
    const float* Wgu_sh = (const float*)d_in[9];
    const float* Wd_sh = (const float*)d_in[10];
    const float* Wgate = (const float*)d_in[11];
    const float* Wgu_ex = (const float*)d_in[12];
    const float* Wd_ex = (const float*)d_in[13];
    float* out = (float*)d_out;

    float *pqkv, *pq, *pkT, *pv, *pscores, *pattn, *ph1, *px2, *psh, *plog, *pye;
    __half *pxh, *pxl, *px2h, *px2l, *phsh, *phsl, *pheh, *phel;
    cudaGetSymbolAddress((void**)&pxh, g_x_h);
    cudaGetSymbolAddress((void**)&pxl, g_x_l);
    cudaGetSymbolAddress((void**)&pqkv, g_qkv);
    cudaGetSymbolAddress((void**)&pq, g_q);
    cudaGetSymbolAddress((void**)&pkT, g_kT);
    cudaGetSymbolAddress((void**)&pv, g_v);
    cudaGetSymbolAddress((void**)&pscores, g_scores);
    cudaGetSymbolAddress((void**)&pattn, g_attn);
    cudaGetSymbolAddress((void**)&ph1, g_h1);
    cudaGetSymbolAddress((void**)&px2, g_x2);
    cudaGetSymbolAddress((void**)&px2h, g_x2_h);
    cudaGetSymbolAddress((void**)&px2l, g_x2_l);
    cudaGetSymbolAddress((void**)&phsh, g_hs_h);
    cudaGetSymbolAddress((void**)&phsl, g_hs_l);
    cudaGetSymbolAddress((void**)&psh, g_sharedo);
    cudaGetSymbolAddress((void**)&plog, g_logits);
    cudaGetSymbolAddress((void**)&pheh, g_hexp_h);
    cudaGetSymbolAddress((void**)&phel, g_hexp_l);
    cudaGetSymbolAddress((void**)&pye, g_ye);

    static int attr_done = 0;
    if (!attr_done) {
        cudaFuncSetAttribute(hf_gemm<0, false, true, 3, false>, cudaFuncAttributeMaxDynamicSharedMemorySize, SM3_BYTES);
        cudaFuncSetAttribute(hf_gemm<0, true, false, 3, false>, cudaFuncAttributeMaxDynamicSharedMemorySize, SM3_BYTES);
        cudaFuncSetAttribute(hf_gemm<0, false, true, 2, true>, cudaFuncAttributeMaxDynamicSharedMemorySize, SM2_BYTES);
        cudaFuncSetAttribute(hf_gemm<0, false, true, 2, false>, cudaFuncAttributeMaxDynamicSharedMemorySize, SM2_BYTES);
        cudaFuncSetAttribute(hf_gemm<1, false, true, 2, true>, cudaFuncAttributeMaxDynamicSharedMemorySize, SM2_BYTES);
        cudaFuncSetAttribute(hf_gemm<2, false, true, 2, false>, cudaFuncAttributeMaxDynamicSharedMemorySize, SM2_BYTES);
        attr_done = 1;
    }

    // 1. x = rmsnorm(hidden, ln1) -> fp16 hi/lo
    rmsnorm_kernel<false><<<SEQ, 256>>>(hidden, ln1_w, nullptr, pxh, pxl);
    // 2. qkv = x @ Wqkv (3-pass: high precision, feeds attention + routing path)
    hf_gemm<0, false, true, 3, false><<<dim3(16, 8), 256, SM3_BYTES>>>(
        pxh, pxl, Wqkv, pqkv, nullptr, nullptr, nullptr, 2048, 1024);
    // 3. rope + qknorm + split
    rope_qk_kernel<<<dim3(SEQ, KVHEADS), 128>>>(cosb, sinb, qnorm_w, knorm_w);
    // 4. scores = q @ k^T (causal block-skip)
    sgemm_kernel<false, 1><<<dim3(8, 8, NHEADS), 256>>>(pq, pkT, pscores, nullptr,
        1024, 1024, 64, 64, 1024, 1024, 65536, 65536, 1048576, 2);
    // 5. causal softmax
    softmax_kernel<<<dim3(SEQ, NHEADS), 256>>>();
    // 6. attn = P @ V (K capped per row-block)
    sgemm_kernel<false, 2><<<dim3(1, 8, NHEADS), 256>>>(pscores, pv, pattn, nullptr,
        1024, 64, 1024, 1024, 64, 1024, 1048576, 65536, 64, 2);
    // 7. h1 = attn @ Wo + hidden (3-pass, A fp32 in-loop split)
    hf_gemm<0, true, false, 3, false><<<dim3(8, 8), 256, SM3_BYTES>>>(
        pattn, nullptr, Wo, ph1, hidden, nullptr, nullptr, 1024, 1024);
    // 8. x2 = rmsnorm(h1, ln2) -> fp32 + fp16 hi/lo
    rmsnorm_kernel<true><<<SEQ, 256>>>(ph1, ln2_w, px2, px2h, px2l);
    // 9+10. hs = swiglu(x2 @ Wgu_shared)  [fused epilogue]
    hf_gemm<0, false, true, 2, true><<<dim3(48, 8), 256, SM2_BYTES>>>(
        px2h, px2l, Wgu_sh, nullptr, nullptr, phsh, phsl, 6144, 1024);
    // 11. shared = hs @ Wd_shared
    hf_gemm<0, false, true, 2, false><<<dim3(8, 8), 256, SM2_BYTES>>>(
        phsh, phsl, Wd_sh, psh, nullptr, nullptr, nullptr, 1024, 3072);
    // 12. logits = x2 @ Wgate (fp32)
    sgemm_kernel<false, 0><<<dim3(1, 8, 1), 256>>>(px2, Wgate, plog, nullptr,
        1024, 64, 1024, 1024, 64, 64, 0, 0, 0, 1);
    // 13. softmax + top8
    topk_kernel<<<SEQ, 64>>>();
    // 14. routing
    route_kernel<<<1, 64>>>();
    // 15+16. hexp = swiglu(gather(x2) @ Wgu_experts)  [fused epilogue]
    hf_gemm<1, false, true, 2, true><<<dim3(48, 256), 256, SM2_BYTES>>>(
        px2h, px2l, Wgu_ex, nullptr, nullptr, pheh, phel, 6144, 1024);
    // 17. ye = hexp @ Wd_experts
    hf_gemm<2, false, true, 2, false><<<dim3(8, 256), 256, SM2_BYTES>>>(
        pheh, phel, Wd_ex, pye, nullptr, nullptr, nullptr, 1024, 3072);
    // 18. out = h1 + shared + moe
    combine_kernel<<<SEQ, 256>>>(out);
}